// round 5
// baseline (speedup 1.0000x reference)
#include <cuda_runtime.h>
#include <cuda_fp16.h>
#include <stdint.h>
#include <math.h>

#define NPTS 200000
#define CCH  128
#define EPSV 1e-5f
#define APITCH 136              // halfs per row (272 bytes)
#define TILEB  (128 * APITCH * 2)  // 34816 bytes per tile buffer

// ---------------- scratch (device globals; no allocations anywhere) ----------
__device__ float  g_x[NPTS * CCH];           // fp32 pooled feats / residual
__device__ float  g_y[NPTS * CCH];           // fp32 conv output
__device__ __half g_xh[NPTS * CCH];          // fp16 conv input (x path)
__device__ __half g_ah[NPTS * CCH];          // fp16 conv input (mid path)
__device__ __half g_wh[4 * 27 * CCH * CCH];  // fp16 conv weights
__device__ float  g_cnt[NPTS];
__device__ float  g_stats[256];              // [0..127]=sum [128..255]=sumsq

// ---------------- helpers ----------------
__device__ __forceinline__ unsigned smem_u32(const void* p) {
    return (unsigned)__cvta_generic_to_shared(p);
}
__device__ __forceinline__ void ldsm_x4(uint32_t* r, unsigned addr) {
    asm volatile("ldmatrix.sync.aligned.m8n8.x4.shared.b16 {%0,%1,%2,%3}, [%4];\n"
                 : "=r"(r[0]), "=r"(r[1]), "=r"(r[2]), "=r"(r[3]) : "r"(addr));
}
__device__ __forceinline__ void ldsm_x4_t(uint32_t* r, unsigned addr) {
    asm volatile("ldmatrix.sync.aligned.m8n8.x4.trans.shared.b16 {%0,%1,%2,%3}, [%4];\n"
                 : "=r"(r[0]), "=r"(r[1]), "=r"(r[2]), "=r"(r[3]) : "r"(addr));
}
__device__ __forceinline__ void mma_f16(float* c, const uint32_t* a, uint32_t b0, uint32_t b1) {
    asm volatile("mma.sync.aligned.m16n8k16.row.col.f32.f16.f16.f32 "
                 "{%0,%1,%2,%3}, {%4,%5,%6,%7}, {%8,%9}, {%0,%1,%2,%3};\n"
                 : "+f"(c[0]), "+f"(c[1]), "+f"(c[2]), "+f"(c[3])
                 : "r"(a[0]), "r"(a[1]), "r"(a[2]), "r"(a[3]), "r"(b0), "r"(b1));
}
__device__ __forceinline__ void cp16(unsigned dst, const void* src) {
    asm volatile("cp.async.cg.shared.global [%0], [%1], 16;\n" :: "r"(dst), "l"(src));
}
__device__ __forceinline__ void cp16z(unsigned dst, const void* src, unsigned ssz) {
    asm volatile("cp.async.cg.shared.global [%0], [%1], 16, %2;\n"
                 :: "r"(dst), "l"(src), "r"(ssz));
}

// ---------------- zero kernels ----------------
__global__ void zero_pool_kernel(float* x, float* cnt, int M) {
    int total = M * CCH;
    for (int i = blockIdx.x * blockDim.x + threadIdx.x; i < total; i += gridDim.x * blockDim.x)
        x[i] = 0.f;
    for (int i = blockIdx.x * blockDim.x + threadIdx.x; i < M; i += gridDim.x * blockDim.x)
        cnt[i] = 0.f;
}
__global__ void zero_stats_kernel(float* stats) { stats[threadIdx.x] = 0.f; }

// ---------------- weight fp32 -> fp16 ----------------
__global__ void convert_w_kernel(const float* __restrict__ w, __half* __restrict__ wh, int n) {
    for (int i = blockIdx.x * blockDim.x + threadIdx.x; i < n; i += gridDim.x * blockDim.x)
        wh[i] = __float2half(w[i]);
}

// ---------------- encoder: warp-per-point Linear+LN+ReLU + segment-sum --------
__global__ __launch_bounds__(256)
void encode_pool_kernel(const float* __restrict__ gp,
                        const float* __restrict__ w_enc,
                        const float* __restrict__ b_enc,
                        const float* __restrict__ ln_g,
                        const float* __restrict__ ln_b,
                        const int*   __restrict__ inv_idx,
                        float* __restrict__ xsum,
                        float* __restrict__ cnt,
                        int Np) {
    const int lane = threadIdx.x & 31;
    const int gw = (blockIdx.x * blockDim.x + threadIdx.x) >> 5;
    const int nw = (gridDim.x * blockDim.x) >> 5;
    const int c0 = lane * 4;

    float wreg[14][4];
#pragma unroll
    for (int k = 0; k < 14; ++k) {
        float4 t = *(const float4*)(w_enc + k * CCH + c0);
        wreg[k][0] = t.x; wreg[k][1] = t.y; wreg[k][2] = t.z; wreg[k][3] = t.w;
    }
    float4 be = *(const float4*)(b_enc + c0);
    float4 lg = *(const float4*)(ln_g + c0);
    float4 lb = *(const float4*)(ln_b + c0);

    for (int i = gw; i < Np; i += nw) {
        float gv = (lane < 14) ? gp[(size_t)i * 14 + lane] : 0.f;
        float f0 = be.x, f1 = be.y, f2 = be.z, f3 = be.w;
#pragma unroll
        for (int k = 0; k < 14; ++k) {
            float s = __shfl_sync(0xffffffffu, gv, k);
            f0 += s * wreg[k][0]; f1 += s * wreg[k][1];
            f2 += s * wreg[k][2]; f3 += s * wreg[k][3];
        }
        float s1 = f0 + f1 + f2 + f3;
        float s2 = f0 * f0 + f1 * f1 + f2 * f2 + f3 * f3;
#pragma unroll
        for (int off = 16; off > 0; off >>= 1) {
            s1 += __shfl_xor_sync(0xffffffffu, s1, off);
            s2 += __shfl_xor_sync(0xffffffffu, s2, off);
        }
        float mu  = s1 * (1.f / 128.f);
        float inv = rsqrtf(s2 * (1.f / 128.f) - mu * mu + EPSV);
        int vox = inv_idx[i];
        float* dst = xsum + (size_t)vox * CCH + c0;
        atomicAdd(dst + 0, fmaxf((f0 - mu) * inv * lg.x + lb.x, 0.f));
        atomicAdd(dst + 1, fmaxf((f1 - mu) * inv * lg.y + lb.y, 0.f));
        atomicAdd(dst + 2, fmaxf((f2 - mu) * inv * lg.z + lb.z, 0.f));
        atomicAdd(dst + 3, fmaxf((f3 - mu) * inv * lg.w + lb.w, 0.f));
        if (lane == 0) atomicAdd(&cnt[vox], 1.f);
    }
}

// ---------------- pooled sums / counts -> fp32 + fp16 -------------------------
__global__ void pool_div_kernel(float* __restrict__ x, const float* __restrict__ cnt,
                                __half* __restrict__ xh, int M) {
    int total = M * CCH;
    for (int i = blockIdx.x * blockDim.x + threadIdx.x; i < total; i += gridDim.x * blockDim.x) {
        float v = x[i] / cnt[i >> 7];
        x[i] = v;
        xh[i] = __float2half(v);
    }
}

// ---------------- submanifold conv, fp16 mma.sync, cp.async double-buffered ---
// 128 voxels x 128 channels per 256-thread block. Warp grid 4(m) x 2(n),
// warp tile 32x64. BN sum/sumsq fused into the epilogue.
__global__ __launch_bounds__(256, 1)
void subm_conv_mma_kernel(const __half* __restrict__ xin,
                          const __half* __restrict__ W,   // 27 x 128 x 128 fp16
                          const int*   __restrict__ nbr_idx,
                          const float* __restrict__ nbr_mask,
                          float* __restrict__ y,
                          float* __restrict__ gstats,
                          int M) {
    extern __shared__ __align__(16) char smem_raw[];
    __half* SA = (__half*)smem_raw;            // 2 x 128 x 136
    __half* SB = SA + 2 * 128 * APITCH;        // 2 x 128 x 136
    int* sidx  = (int*)(SB + 2 * 128 * APITCH);  // 27 x 128 (idx or -1)
    __shared__ int   s_act[27], s_sal[27], s_nact;
    __shared__ float sstat[CCH], ssq[CCH];

    const int tid  = threadIdx.x;
    const int warp = tid >> 5, lane = tid & 31;
    const int wm = warp & 3;          // rows wm*32 .. +31
    const int wn = warp >> 2;         // cols wn*64 .. +63
    const int v0 = blockIdx.x * 128;

    // ---- prologue: coalesced gather of idx/mask, build active-offset list ----
    for (int j = tid; j < 27 * 128; j += 256) {
        int r = j / 27, o = j - r * 27;
        int v = v0 + r;
        int id = -1;
        if (v < M && nbr_mask[(size_t)v0 * 27 + j] != 0.f)
            id = nbr_idx[(size_t)v0 * 27 + j];
        sidx[o * 128 + r] = id;
    }
    if (tid < 27) s_act[tid] = 0;
    if (tid < CCH) { sstat[tid] = 0.f; ssq[tid] = 0.f; }
    __syncthreads();
    if (warp < 4) {
        for (int o = 0; o < 27; ++o) {
            unsigned bal = __ballot_sync(0xffffffffu, sidx[o * 128 + warp * 32 + lane] >= 0);
            if (lane == 0 && bal) s_act[o] = 1;
        }
    }
    __syncthreads();
    if (tid == 0) {
        int n = 0;
        for (int o = 0; o < 27; ++o) if (s_act[o]) s_sal[n++] = o;
        s_nact = n;
    }
    __syncthreads();
    const int nact = s_nact;

    const unsigned sAu = smem_u32(SA);
    const unsigned sBu = smem_u32(SB);
    const int r  = tid >> 1;          // staging row 0..127
    const int hf = tid & 1;           // half-row 0/1
    const unsigned stoff = (unsigned)(r * (APITCH * 2) + hf * 128);

    float acc[2][8][4];
#pragma unroll
    for (int mi = 0; mi < 2; ++mi)
#pragma unroll
        for (int ni = 0; ni < 8; ++ni)
#pragma unroll
            for (int q = 0; q < 4; ++q) acc[mi][ni][q] = 0.f;

    // ---- stage offset 0 into buffer 0 ----
    {
        int o = s_sal[0];
        int id = sidx[o * 128 + r];
        unsigned ssz = (id >= 0) ? 16u : 0u;
        const __half* srcA = xin + (size_t)(id >= 0 ? id : 0) * CCH + hf * 64;
        const __half* srcB = W + (size_t)o * CCH * CCH + r * CCH + hf * 64;
#pragma unroll
        for (int q = 0; q < 8; ++q) {
            cp16z(sAu + stoff + q * 16, srcA + q * 8, ssz);
            cp16 (sBu + stoff + q * 16, srcB + q * 8);
        }
        asm volatile("cp.async.commit_group;\n" ::: "memory");
    }

    for (int t = 0; t < nact; ++t) {
        const int b = t & 1;
        if (t + 1 < nact) {
            // stage t+1 into the other buffer, then wait for t's group
            int o = s_sal[t + 1];
            int id = sidx[o * 128 + r];
            unsigned ssz = (id >= 0) ? 16u : 0u;
            const __half* srcA = xin + (size_t)(id >= 0 ? id : 0) * CCH + hf * 64;
            const __half* srcB = W + (size_t)o * CCH * CCH + r * CCH + hf * 64;
            unsigned dA = sAu + (unsigned)((b ^ 1) * TILEB) + stoff;
            unsigned dB = sBu + (unsigned)((b ^ 1) * TILEB) + stoff;
#pragma unroll
            for (int q = 0; q < 8; ++q) {
                cp16z(dA + q * 16, srcA + q * 8, ssz);
                cp16 (dB + q * 16, srcB + q * 8);
            }
            asm volatile("cp.async.commit_group;\n" ::: "memory");
            asm volatile("cp.async.wait_group 1;\n" ::: "memory");
        } else {
            asm volatile("cp.async.wait_group 0;\n" ::: "memory");
        }
        __syncthreads();

        const unsigned Ab = sAu + (unsigned)(b * TILEB);
        const unsigned Bb = sBu + (unsigned)(b * TILEB);
#pragma unroll
        for (int kc = 0; kc < 8; ++kc) {
            uint32_t a[2][4];
#pragma unroll
            for (int mi = 0; mi < 2; ++mi) {
                unsigned p = Ab + (unsigned)((wm * 32 + mi * 16 + (lane & 15)) * (APITCH * 2)
                                             + (kc * 16 + (lane >> 4) * 8) * 2);
                ldsm_x4(a[mi], p);
            }
#pragma unroll
            for (int nb = 0; nb < 4; ++nb) {
                uint32_t bb[4];
                unsigned p = Bb + (unsigned)((kc * 16 + (lane & 15)) * (APITCH * 2)
                                             + (wn * 64 + nb * 16 + (lane >> 4) * 8) * 2);
                ldsm_x4_t(bb, p);
#pragma unroll
                for (int mi = 0; mi < 2; ++mi) {
                    mma_f16(acc[mi][nb * 2 + 0], a[mi], bb[0], bb[1]);
                    mma_f16(acc[mi][nb * 2 + 1], a[mi], bb[2], bb[3]);
                }
            }
        }
        __syncthreads();
    }

    // ---- epilogue: store y + fused BN partials (rows >= M are exact zeros) ----
    const int rbase = v0 + wm * 32 + (lane >> 2);
    const int cbase = wn * 64 + (lane & 3) * 2;
#pragma unroll
    for (int mi = 0; mi < 2; ++mi) {
#pragma unroll
        for (int ni = 0; ni < 8; ++ni) {
            int col = cbase + ni * 8;
            int r0 = rbase + mi * 16;
            if (r0 < M) {
                y[(size_t)r0 * CCH + col]     = acc[mi][ni][0];
                y[(size_t)r0 * CCH + col + 1] = acc[mi][ni][1];
            }
            int r1 = r0 + 8;
            if (r1 < M) {
                y[(size_t)r1 * CCH + col]     = acc[mi][ni][2];
                y[(size_t)r1 * CCH + col + 1] = acc[mi][ni][3];
            }
        }
    }
#pragma unroll
    for (int ni = 0; ni < 8; ++ni) {
#pragma unroll
        for (int tt = 0; tt < 2; ++tt) {
            float a0 = acc[0][ni][tt],     a1 = acc[0][ni][2 + tt];
            float a2 = acc[1][ni][tt],     a3 = acc[1][ni][2 + tt];
            float s = a0 + a1 + a2 + a3;
            float q = a0 * a0 + a1 * a1 + a2 * a2 + a3 * a3;
            int c = cbase + ni * 8 + tt;
            atomicAdd(&sstat[c], s);
            atomicAdd(&ssq[c], q);
        }
    }
    __syncthreads();
    if (tid < CCH) {
        atomicAdd(&gstats[tid],       sstat[tid]);
        atomicAdd(&gstats[CCH + tid], ssq[tid]);
    }
}

// ---------------- BN apply (+optional residual) + ReLU, fp32/fp16 out ---------
__global__ void bn_apply_kernel(const float* __restrict__ y,
                                const float* __restrict__ g,
                                const float* __restrict__ b,
                                const float* __restrict__ stats,
                                const float* __restrict__ residual,   // nullable
                                float* __restrict__ out_f32,          // nullable
                                __half* __restrict__ out_h16,         // nullable
                                int M) {
    int total = M * CCH;
    float invM = 1.f / (float)M;
    for (int i = blockIdx.x * blockDim.x + threadIdx.x; i < total; i += gridDim.x * blockDim.x) {
        int c = i & 127;
        float m   = stats[c] * invM;
        float var = stats[128 + c] * invM - m * m;
        float inv = rsqrtf(var + EPSV);
        float v = (y[i] - m) * inv * g[c] + b[c];
        if (residual) v += residual[i];
        v = fmaxf(v, 0.f);
        if (out_f32) out_f32[i] = v;
        if (out_h16) out_h16[i] = __float2half(v);
    }
}

// ---------------- head: gather + MLP(128->64->14) + residual add --------------
__global__ __launch_bounds__(128)
void head_kernel(const float* __restrict__ x,
                 const float* __restrict__ gp,
                 const int*   __restrict__ inv_idx,
                 const float* __restrict__ w1, const float* __restrict__ b1,
                 const float* __restrict__ w2, const float* __restrict__ b2,
                 float* __restrict__ out, int Np) {
    __shared__ float w1s[CCH * 64];
    __shared__ float w2s[64 * 14];
    __shared__ float b1s[64];
    __shared__ float b2s[14];
    __shared__ float pfs[2][CCH];
    __shared__ float hs[2][64];

    const int tid = threadIdx.x;
    for (int i = tid; i < CCH * 64; i += 128) w1s[i] = w1[i];
    for (int i = tid; i < 64 * 14; i += 128) w2s[i] = w2[i];
    if (tid < 64) b1s[tid] = b1[tid];
    if (tid < 14) b2s[tid] = b2[tid];
    __syncthreads();

    const int h = tid >> 6;
    const int j = tid & 63;

    for (int ip = blockIdx.x * 2; ip < Np; ip += gridDim.x * 2) {
        int i = ip + h;
        bool ok = (i < Np);
        if (ok) {
            int v = inv_idx[i];
            pfs[h][j]      = x[(size_t)v * CCH + j];
            pfs[h][j + 64] = x[(size_t)v * CCH + j + 64];
        }
        __syncthreads();
        if (ok) {
            float acc = b1s[j];
#pragma unroll 8
            for (int k = 0; k < CCH; ++k) acc += pfs[h][k] * w1s[k * 64 + j];
            hs[h][j] = fmaxf(acc, 0.f);
        }
        __syncthreads();
        if (ok && j < 14) {
            float d = b2s[j];
#pragma unroll
            for (int k = 0; k < 64; ++k) d += hs[h][k] * w2s[k * 14 + j];
            out[(size_t)i * 14 + j] = gp[(size_t)i * 14 + j] + d;
        }
        __syncthreads();
    }
}

// ---------------- launch -------------------------------------------------------
extern "C" void kernel_launch(void* const* d_in, const int* in_sizes, int n_in,
                              void* d_out, int out_size) {
    const float* gp       = (const float*)d_in[0];
    const float* w_enc    = (const float*)d_in[1];
    const float* b_enc    = (const float*)d_in[2];
    const float* ln_g     = (const float*)d_in[3];
    const float* ln_b     = (const float*)d_in[4];
    const float* conv_w   = (const float*)d_in[5];
    const float* bn_g     = (const float*)d_in[6];
    const float* bn_b     = (const float*)d_in[7];
    const float* w1       = (const float*)d_in[8];
    const float* b1       = (const float*)d_in[9];
    const float* w2       = (const float*)d_in[10];
    const float* b2       = (const float*)d_in[11];
    const float* nbr_mask = (const float*)d_in[12];
    const int*   inv_idx  = (const int*)d_in[13];
    const int*   nbr_idx  = (const int*)d_in[14];
    float* out = (float*)d_out;

    const int Np = in_sizes[0] / 14;
    const int M  = in_sizes[12] / 27;

    float *px, *py, *pcnt, *pstats;
    __half *pxh, *pah, *pwh;
    cudaGetSymbolAddress((void**)&px,     g_x);
    cudaGetSymbolAddress((void**)&py,     g_y);
    cudaGetSymbolAddress((void**)&pxh,    g_xh);
    cudaGetSymbolAddress((void**)&pah,    g_ah);
    cudaGetSymbolAddress((void**)&pwh,    g_wh);
    cudaGetSymbolAddress((void**)&pcnt,   g_cnt);
    cudaGetSymbolAddress((void**)&pstats, g_stats);

    const int CONV_SMEM = 4 * TILEB + 27 * 128 * 4;   // 139264 + 13824 = 153088
    cudaFuncSetAttribute(subm_conv_mma_kernel,
                         cudaFuncAttributeMaxDynamicSharedMemorySize, CONV_SMEM);

    convert_w_kernel<<<1024, 256>>>(conv_w, pwh, 4 * 27 * CCH * CCH);
    zero_pool_kernel<<<1024, 256>>>(px, pcnt, M);
    encode_pool_kernel<<<512, 256>>>(gp, w_enc, b_enc, ln_g, ln_b, inv_idx, px, pcnt, Np);
    pool_div_kernel<<<2048, 256>>>(px, pcnt, pxh, M);

    const int tiles = (M + 127) / 128;
    for (int blk = 0; blk < 2; ++blk) {
        const int l0 = 2 * blk, l1 = 2 * blk + 1;
        // conv1 (fused BN stats) -> BN apply -> ReLU (fp16 out)
        zero_stats_kernel<<<1, 256>>>(pstats);
        subm_conv_mma_kernel<<<tiles, 256, CONV_SMEM>>>(
            pxh, pwh + (size_t)l0 * 27 * CCH * CCH, nbr_idx, nbr_mask, py, pstats, M);
        bn_apply_kernel<<<2048, 256>>>(py, bn_g + l0 * CCH, bn_b + l0 * CCH, pstats,
                                       (const float*)0, (float*)0, pah, M);
        // conv2 (fused BN stats) -> BN apply + residual -> ReLU (fp32 + fp16)
        zero_stats_kernel<<<1, 256>>>(pstats);
        subm_conv_mma_kernel<<<tiles, 256, CONV_SMEM>>>(
            pah, pwh + (size_t)l1 * 27 * CCH * CCH, nbr_idx, nbr_mask, py, pstats, M);
        bn_apply_kernel<<<2048, 256>>>(py, bn_g + l1 * CCH, bn_b + l1 * CCH, pstats,
                                       px, px, pxh, M);
    }

    head_kernel<<<2048, 128>>>(px, gp, inv_idx, w1, b1, w2, b2, out, Np);
}

// round 6
// speedup vs baseline: 1.1425x; 1.1425x over previous
#include <cuda_runtime.h>
#include <cuda_fp16.h>
#include <stdint.h>
#include <math.h>

#define NPTS 200000
#define CCH  128
#define EPSV 1e-5f
#define TILEB 32768u            // 128 x 128 halfs, swizzled (no padding)

// ---------------- scratch (device globals; no allocations anywhere) ----------
__device__ float  g_x[NPTS * CCH];           // fp32 pooled feats / residual
__device__ float  g_y[NPTS * CCH];           // fp32 conv output
__device__ __half g_xh[NPTS * CCH];          // fp16 conv input (x path)
__device__ __half g_ah[NPTS * CCH];          // fp16 conv input (mid path)
__device__ __half g_wh[4 * 27 * CCH * CCH];  // fp16 conv weights
__device__ float  g_cnt[NPTS];
__device__ float  g_stats[256];              // [0..127]=sum [128..255]=sumsq

// ---------------- helpers ----------------
__device__ __forceinline__ unsigned smem_u32(const void* p) {
    return (unsigned)__cvta_generic_to_shared(p);
}
// swizzled byte offset within a 128x128-half tile: row-major, 16 chunks of 16B
// per row, chunk index XORed with (row & 7) -> conflict-free ldmatrix + stores
__device__ __forceinline__ unsigned swz(int row, int c16) {
    return (unsigned)(row * 256 + (((c16) ^ (row & 7)) << 4));
}
__device__ __forceinline__ void ldsm_x4(uint32_t* r, unsigned addr) {
    asm volatile("ldmatrix.sync.aligned.m8n8.x4.shared.b16 {%0,%1,%2,%3}, [%4];\n"
                 : "=r"(r[0]), "=r"(r[1]), "=r"(r[2]), "=r"(r[3]) : "r"(addr));
}
__device__ __forceinline__ void ldsm_x4_t(uint32_t* r, unsigned addr) {
    asm volatile("ldmatrix.sync.aligned.m8n8.x4.trans.shared.b16 {%0,%1,%2,%3}, [%4];\n"
                 : "=r"(r[0]), "=r"(r[1]), "=r"(r[2]), "=r"(r[3]) : "r"(addr));
}
__device__ __forceinline__ void mma_f16(float* c, const uint32_t* a, uint32_t b0, uint32_t b1) {
    asm volatile("mma.sync.aligned.m16n8k16.row.col.f32.f16.f16.f32 "
                 "{%0,%1,%2,%3}, {%4,%5,%6,%7}, {%8,%9}, {%0,%1,%2,%3};\n"
                 : "+f"(c[0]), "+f"(c[1]), "+f"(c[2]), "+f"(c[3])
                 : "r"(a[0]), "r"(a[1]), "r"(a[2]), "r"(a[3]), "r"(b0), "r"(b1));
}
__device__ __forceinline__ void cp16(unsigned dst, const void* src) {
    asm volatile("cp.async.cg.shared.global [%0], [%1], 16;\n" :: "r"(dst), "l"(src));
}
__device__ __forceinline__ void cp16z(unsigned dst, const void* src, unsigned ssz) {
    asm volatile("cp.async.cg.shared.global [%0], [%1], 16, %2;\n"
                 :: "r"(dst), "l"(src), "r"(ssz));
}

// ---------------- zero kernels ----------------
__global__ void zero_pool_kernel(float* x, float* cnt, int M) {
    int total = M * CCH;
    for (int i = blockIdx.x * blockDim.x + threadIdx.x; i < total; i += gridDim.x * blockDim.x)
        x[i] = 0.f;
    for (int i = blockIdx.x * blockDim.x + threadIdx.x; i < M; i += gridDim.x * blockDim.x)
        cnt[i] = 0.f;
}
__global__ void zero_stats_kernel(float* stats) { stats[threadIdx.x] = 0.f; }

// ---------------- weight fp32 -> fp16 ----------------
__global__ void convert_w_kernel(const float* __restrict__ w, __half* __restrict__ wh, int n) {
    for (int i = blockIdx.x * blockDim.x + threadIdx.x; i < n; i += gridDim.x * blockDim.x)
        wh[i] = __float2half(w[i]);
}

// ---------------- encoder: warp-per-point Linear+LN+ReLU + segment-sum --------
__global__ __launch_bounds__(256)
void encode_pool_kernel(const float* __restrict__ gp,
                        const float* __restrict__ w_enc,
                        const float* __restrict__ b_enc,
                        const float* __restrict__ ln_g,
                        const float* __restrict__ ln_b,
                        const int*   __restrict__ inv_idx,
                        float* __restrict__ xsum,
                        float* __restrict__ cnt,
                        int Np) {
    const int lane = threadIdx.x & 31;
    const int gw = (blockIdx.x * blockDim.x + threadIdx.x) >> 5;
    const int nw = (gridDim.x * blockDim.x) >> 5;
    const int c0 = lane * 4;

    float wreg[14][4];
#pragma unroll
    for (int k = 0; k < 14; ++k) {
        float4 t = *(const float4*)(w_enc + k * CCH + c0);
        wreg[k][0] = t.x; wreg[k][1] = t.y; wreg[k][2] = t.z; wreg[k][3] = t.w;
    }
    float4 be = *(const float4*)(b_enc + c0);
    float4 lg = *(const float4*)(ln_g + c0);
    float4 lb = *(const float4*)(ln_b + c0);

    for (int i = gw; i < Np; i += nw) {
        float gv = (lane < 14) ? gp[(size_t)i * 14 + lane] : 0.f;
        float f0 = be.x, f1 = be.y, f2 = be.z, f3 = be.w;
#pragma unroll
        for (int k = 0; k < 14; ++k) {
            float s = __shfl_sync(0xffffffffu, gv, k);
            f0 += s * wreg[k][0]; f1 += s * wreg[k][1];
            f2 += s * wreg[k][2]; f3 += s * wreg[k][3];
        }
        float s1 = f0 + f1 + f2 + f3;
        float s2 = f0 * f0 + f1 * f1 + f2 * f2 + f3 * f3;
#pragma unroll
        for (int off = 16; off > 0; off >>= 1) {
            s1 += __shfl_xor_sync(0xffffffffu, s1, off);
            s2 += __shfl_xor_sync(0xffffffffu, s2, off);
        }
        float mu  = s1 * (1.f / 128.f);
        float inv = rsqrtf(s2 * (1.f / 128.f) - mu * mu + EPSV);
        int vox = inv_idx[i];
        float* dst = xsum + (size_t)vox * CCH + c0;
        atomicAdd(dst + 0, fmaxf((f0 - mu) * inv * lg.x + lb.x, 0.f));
        atomicAdd(dst + 1, fmaxf((f1 - mu) * inv * lg.y + lb.y, 0.f));
        atomicAdd(dst + 2, fmaxf((f2 - mu) * inv * lg.z + lb.z, 0.f));
        atomicAdd(dst + 3, fmaxf((f3 - mu) * inv * lg.w + lb.w, 0.f));
        if (lane == 0) atomicAdd(&cnt[vox], 1.f);
    }
}

// ---------------- pooled sums / counts -> fp32 + fp16 -------------------------
__global__ void pool_div_kernel(float* __restrict__ x, const float* __restrict__ cnt,
                                __half* __restrict__ xh, int M) {
    int total = M * CCH;
    for (int i = blockIdx.x * blockDim.x + threadIdx.x; i < total; i += gridDim.x * blockDim.x) {
        float v = x[i] / cnt[i >> 7];
        x[i] = v;
        xh[i] = __float2half(v);
    }
}

// ---------------- submanifold conv, fp16 mma.sync, cp.async double-buffered ---
// 128 voxels x 128 channels per 512-thread block (16 warps, 4x4 grid, 32x32
// warp tiles). XOR-swizzled smem. BN sum/sumsq fused into the epilogue.
__global__ __launch_bounds__(512, 1)
void subm_conv_mma_kernel(const __half* __restrict__ xin,
                          const __half* __restrict__ W,   // 27 x 128 x 128 fp16
                          const int*   __restrict__ nbr_idx,
                          const float* __restrict__ nbr_mask,
                          float* __restrict__ y,
                          float* __restrict__ gstats,
                          int M) {
    extern __shared__ __align__(16) char smem_raw[];
    // layout: A0 @0, A1 @32K, B0 @64K, B1 @96K, sidx @128K
    int* sidx = (int*)(smem_raw + 4 * TILEB);   // 27 x 128
    __shared__ int   s_act[27], s_sal[27], s_nact;
    __shared__ float sstat[CCH], ssq[CCH];

    const int tid  = threadIdx.x;
    const int warp = tid >> 5, lane = tid & 31;
    const int wm = warp & 3;          // rows wm*32 .. +31
    const int wn = warp >> 2;         // cols wn*32 .. +31
    const int v0 = blockIdx.x * 128;

    // ---- prologue: gather idx/mask, build active-offset list ----
    for (int j = tid; j < 27 * 128; j += 512) {
        int r = j / 27, o = j - r * 27;
        int v = v0 + r;
        int id = -1;
        if (v < M && nbr_mask[(size_t)v0 * 27 + j] != 0.f)
            id = nbr_idx[(size_t)v0 * 27 + j];
        sidx[o * 128 + r] = id;
    }
    if (tid < 27) s_act[tid] = 0;
    if (tid < CCH) { sstat[tid] = 0.f; ssq[tid] = 0.f; }
    __syncthreads();
    if (warp < 4) {
#pragma unroll 1
        for (int o = 0; o < 27; ++o) {
            unsigned bal = __ballot_sync(0xffffffffu, sidx[o * 128 + warp * 32 + lane] >= 0);
            if (lane == 0 && bal) s_act[o] = 1;
        }
    }
    __syncthreads();
    if (tid == 0) {
        int n = 0;
        for (int o = 0; o < 27; ++o) if (s_act[o]) s_sal[n++] = o;
        s_nact = n;
    }
    __syncthreads();
    const int nact = s_nact;

    const unsigned sAu = smem_u32(smem_raw);
    const unsigned sBu = sAu + 2 * TILEB;
    const int srow = tid >> 2;            // staging row 0..127
    const int sc0  = (tid & 3) * 4;       // 4 of the 16 16B-chunks per row

    float acc[2][4][4];
#pragma unroll
    for (int mi = 0; mi < 2; ++mi)
#pragma unroll
        for (int ni = 0; ni < 4; ++ni)
#pragma unroll
            for (int q = 0; q < 4; ++q) acc[mi][ni][q] = 0.f;

    // ---- stage offset 0 into buffer 0 ----
    {
        int o = s_sal[0];
        int id = sidx[o * 128 + srow];
        unsigned ssz = (id >= 0) ? 16u : 0u;
        const __half* srcA = xin + (size_t)(id >= 0 ? id : 0) * CCH + sc0 * 8;
        const __half* srcB = W + (size_t)o * CCH * CCH + srow * CCH + sc0 * 8;
#pragma unroll
        for (int q = 0; q < 4; ++q) {
            cp16z(sAu + swz(srow, sc0 + q), srcA + q * 8, ssz);
            cp16 (sBu + swz(srow, sc0 + q), srcB + q * 8);
        }
        asm volatile("cp.async.commit_group;\n" ::: "memory");
    }

    for (int t = 0; t < nact; ++t) {
        const int b = t & 1;
        if (t + 1 < nact) {
            int o = s_sal[t + 1];
            int id = sidx[o * 128 + srow];
            unsigned ssz = (id >= 0) ? 16u : 0u;
            const __half* srcA = xin + (size_t)(id >= 0 ? id : 0) * CCH + sc0 * 8;
            const __half* srcB = W + (size_t)o * CCH * CCH + srow * CCH + sc0 * 8;
            unsigned dA = sAu + (unsigned)((b ^ 1) * TILEB);
            unsigned dB = sBu + (unsigned)((b ^ 1) * TILEB);
#pragma unroll
            for (int q = 0; q < 4; ++q) {
                cp16z(dA + swz(srow, sc0 + q), srcA + q * 8, ssz);
                cp16 (dB + swz(srow, sc0 + q), srcB + q * 8);
            }
            asm volatile("cp.async.commit_group;\n" ::: "memory");
            asm volatile("cp.async.wait_group 1;\n" ::: "memory");
        } else {
            asm volatile("cp.async.wait_group 0;\n" ::: "memory");
        }
        __syncthreads();

        const unsigned Ab = sAu + (unsigned)(b * TILEB);
        const unsigned Bb = sBu + (unsigned)(b * TILEB);
#pragma unroll
        for (int kc = 0; kc < 8; ++kc) {
            uint32_t a[2][4];
#pragma unroll
            for (int mi = 0; mi < 2; ++mi) {
                int row = wm * 32 + mi * 16 + (lane & 15);
                ldsm_x4(a[mi], Ab + swz(row, kc * 2 + (lane >> 4)));
            }
#pragma unroll
            for (int nb = 0; nb < 2; ++nb) {
                uint32_t bb[4];
                int row = kc * 16 + (lane & 15);
                ldsm_x4_t(bb, Bb + swz(row, wn * 4 + nb * 2 + (lane >> 4)));
#pragma unroll
                for (int mi = 0; mi < 2; ++mi) {
                    mma_f16(acc[mi][nb * 2 + 0], a[mi], bb[0], bb[1]);
                    mma_f16(acc[mi][nb * 2 + 1], a[mi], bb[2], bb[3]);
                }
            }
        }
        __syncthreads();
    }

    // ---- epilogue: store y + fused BN partials (rows >= M are exact zeros) ----
    const int rbase = v0 + wm * 32 + (lane >> 2);
    const int cbase = wn * 32 + (lane & 3) * 2;
#pragma unroll
    for (int mi = 0; mi < 2; ++mi) {
#pragma unroll
        for (int ni = 0; ni < 4; ++ni) {
            int col = cbase + ni * 8;
            int r0 = rbase + mi * 16;
            if (r0 < M) {
                y[(size_t)r0 * CCH + col]     = acc[mi][ni][0];
                y[(size_t)r0 * CCH + col + 1] = acc[mi][ni][1];
            }
            int r1 = r0 + 8;
            if (r1 < M) {
                y[(size_t)r1 * CCH + col]     = acc[mi][ni][2];
                y[(size_t)r1 * CCH + col + 1] = acc[mi][ni][3];
            }
        }
    }
#pragma unroll
    for (int ni = 0; ni < 4; ++ni) {
#pragma unroll
        for (int tt = 0; tt < 2; ++tt) {
            float a0 = acc[0][ni][tt],     a1 = acc[0][ni][2 + tt];
            float a2 = acc[1][ni][tt],     a3 = acc[1][ni][2 + tt];
            float s = a0 + a1 + a2 + a3;
            float q = a0 * a0 + a1 * a1 + a2 * a2 + a3 * a3;
            int c = cbase + ni * 8 + tt;
            atomicAdd(&sstat[c], s);
            atomicAdd(&ssq[c], q);
        }
    }
    __syncthreads();
    if (tid < CCH) {
        atomicAdd(&gstats[tid],       sstat[tid]);
        atomicAdd(&gstats[CCH + tid], ssq[tid]);
    }
}

// ---------------- BN apply (+optional residual) + ReLU, fp32/fp16 out ---------
__global__ void bn_apply_kernel(const float* __restrict__ y,
                                const float* __restrict__ g,
                                const float* __restrict__ b,
                                const float* __restrict__ stats,
                                const float* __restrict__ residual,   // nullable
                                float* __restrict__ out_f32,          // nullable
                                __half* __restrict__ out_h16,         // nullable
                                int M) {
    int total = M * CCH;
    float invM = 1.f / (float)M;
    for (int i = blockIdx.x * blockDim.x + threadIdx.x; i < total; i += gridDim.x * blockDim.x) {
        int c = i & 127;
        float m   = stats[c] * invM;
        float var = stats[128 + c] * invM - m * m;
        float inv = rsqrtf(var + EPSV);
        float v = (y[i] - m) * inv * g[c] + b[c];
        if (residual) v += residual[i];
        v = fmaxf(v, 0.f);
        if (out_f32) out_f32[i] = v;
        if (out_h16) out_h16[i] = __float2half(v);
    }
}

// ---------------- head: gather + MLP(128->64->14) + residual add --------------
__global__ __launch_bounds__(128)
void head_kernel(const float* __restrict__ x,
                 const float* __restrict__ gp,
                 const int*   __restrict__ inv_idx,
                 const float* __restrict__ w1, const float* __restrict__ b1,
                 const float* __restrict__ w2, const float* __restrict__ b2,
                 float* __restrict__ out, int Np) {
    __shared__ float w1s[CCH * 64];
    __shared__ float w2s[64 * 14];
    __shared__ float b1s[64];
    __shared__ float b2s[14];
    __shared__ float pfs[2][CCH];
    __shared__ float hs[2][64];

    const int tid = threadIdx.x;
    for (int i = tid; i < CCH * 64; i += 128) w1s[i] = w1[i];
    for (int i = tid; i < 64 * 14; i += 128) w2s[i] = w2[i];
    if (tid < 64) b1s[tid] = b1[tid];
    if (tid < 14) b2s[tid] = b2[tid];
    __syncthreads();

    const int h = tid >> 6;
    const int j = tid & 63;

    for (int ip = blockIdx.x * 2; ip < Np; ip += gridDim.x * 2) {
        int i = ip + h;
        bool ok = (i < Np);
        if (ok) {
            int v = inv_idx[i];
            pfs[h][j]      = x[(size_t)v * CCH + j];
            pfs[h][j + 64] = x[(size_t)v * CCH + j + 64];
        }
        __syncthreads();
        if (ok) {
            float acc = b1s[j];
#pragma unroll 8
            for (int k = 0; k < CCH; ++k) acc += pfs[h][k] * w1s[k * 64 + j];
            hs[h][j] = fmaxf(acc, 0.f);
        }
        __syncthreads();
        if (ok && j < 14) {
            float d = b2s[j];
#pragma unroll
            for (int k = 0; k < 64; ++k) d += hs[h][k] * w2s[k * 14 + j];
            out[(size_t)i * 14 + j] = gp[(size_t)i * 14 + j] + d;
        }
        __syncthreads();
    }
}

// ---------------- launch -------------------------------------------------------
extern "C" void kernel_launch(void* const* d_in, const int* in_sizes, int n_in,
                              void* d_out, int out_size) {
    const float* gp       = (const float*)d_in[0];
    const float* w_enc    = (const float*)d_in[1];
    const float* b_enc    = (const float*)d_in[2];
    const float* ln_g     = (const float*)d_in[3];
    const float* ln_b     = (const float*)d_in[4];
    const float* conv_w   = (const float*)d_in[5];
    const float* bn_g     = (const float*)d_in[6];
    const float* bn_b     = (const float*)d_in[7];
    const float* w1       = (const float*)d_in[8];
    const float* b1       = (const float*)d_in[9];
    const float* w2       = (const float*)d_in[10];
    const float* b2       = (const float*)d_in[11];
    const float* nbr_mask = (const float*)d_in[12];
    const int*   inv_idx  = (const int*)d_in[13];
    const int*   nbr_idx  = (const int*)d_in[14];
    float* out = (float*)d_out;

    const int Np = in_sizes[0] / 14;
    const int M  = in_sizes[12] / 27;

    float *px, *py, *pcnt, *pstats;
    __half *pxh, *pah, *pwh;
    cudaGetSymbolAddress((void**)&px,     g_x);
    cudaGetSymbolAddress((void**)&py,     g_y);
    cudaGetSymbolAddress((void**)&pxh,    g_xh);
    cudaGetSymbolAddress((void**)&pah,    g_ah);
    cudaGetSymbolAddress((void**)&pwh,    g_wh);
    cudaGetSymbolAddress((void**)&pcnt,   g_cnt);
    cudaGetSymbolAddress((void**)&pstats, g_stats);

    const int CONV_SMEM = 4 * TILEB + 27 * 128 * 4;   // 131072 + 13824 = 144896
    cudaFuncSetAttribute(subm_conv_mma_kernel,
                         cudaFuncAttributeMaxDynamicSharedMemorySize, CONV_SMEM);

    convert_w_kernel<<<1024, 256>>>(conv_w, pwh, 4 * 27 * CCH * CCH);
    zero_pool_kernel<<<1024, 256>>>(px, pcnt, M);
    encode_pool_kernel<<<512, 256>>>(gp, w_enc, b_enc, ln_g, ln_b, inv_idx, px, pcnt, Np);
    pool_div_kernel<<<2048, 256>>>(px, pcnt, pxh, M);

    const int tiles = (M + 127) / 128;
    for (int blk = 0; blk < 2; ++blk) {
        const int l0 = 2 * blk, l1 = 2 * blk + 1;
        // conv1 (fused BN stats) -> BN apply -> ReLU (fp16 out)
        zero_stats_kernel<<<1, 256>>>(pstats);
        subm_conv_mma_kernel<<<tiles, 512, CONV_SMEM>>>(
            pxh, pwh + (size_t)l0 * 27 * CCH * CCH, nbr_idx, nbr_mask, py, pstats, M);
        bn_apply_kernel<<<2048, 256>>>(py, bn_g + l0 * CCH, bn_b + l0 * CCH, pstats,
                                       (const float*)0, (float*)0, pah, M);
        // conv2 (fused BN stats) -> BN apply + residual -> ReLU (fp32 + fp16)
        zero_stats_kernel<<<1, 256>>>(pstats);
        subm_conv_mma_kernel<<<tiles, 512, CONV_SMEM>>>(
            pah, pwh + (size_t)l1 * 27 * CCH * CCH, nbr_idx, nbr_mask, py, pstats, M);
        bn_apply_kernel<<<2048, 256>>>(py, bn_g + l1 * CCH, bn_b + l1 * CCH, pstats,
                                       px, px, pxh, M);
    }

    head_kernel<<<2048, 128>>>(px, gp, inv_idx, w1, b1, w2, b2, out, Np);
}

// round 7
// speedup vs baseline: 1.3874x; 1.2143x over previous
#include <cuda_runtime.h>
#include <cuda_fp16.h>
#include <stdint.h>
#include <math.h>

#define NPTS 200000
#define CCH  128
#define EPSV 1e-5f
#define ATILE 65536u            // 256 x 128 halfs, swizzled
#define BTILE 32768u            // 128 x 128 halfs, swizzled
#define BM    256

// ---------------- scratch (device globals; no allocations anywhere) ----------
__device__ float  g_x[NPTS * CCH];           // fp32 pooled feats / residual
__device__ float  g_y[NPTS * CCH];           // fp32 conv output
__device__ __half g_xh[NPTS * CCH];          // fp16 conv input (x path)
__device__ __half g_ah[NPTS * CCH];          // fp16 conv input (mid path)
__device__ __half g_wh[4 * 27 * CCH * CCH];  // fp16 conv weights
__device__ float  g_cnt[NPTS];
__device__ float  g_stats[256];              // [0..127]=sum [128..255]=sumsq

// ---------------- helpers ----------------
__device__ __forceinline__ unsigned smem_u32(const void* p) {
    return (unsigned)__cvta_generic_to_shared(p);
}
// swizzled byte offset within a row-major tile of 128-half rows:
// 16 chunks of 16B per row, chunk index XORed with (row & 7)
__device__ __forceinline__ unsigned swz(int row, int c16) {
    return (unsigned)(row * 256 + (((c16) ^ (row & 7)) << 4));
}
__device__ __forceinline__ void ldsm_x4(uint32_t* r, unsigned addr) {
    asm volatile("ldmatrix.sync.aligned.m8n8.x4.shared.b16 {%0,%1,%2,%3}, [%4];\n"
                 : "=r"(r[0]), "=r"(r[1]), "=r"(r[2]), "=r"(r[3]) : "r"(addr));
}
__device__ __forceinline__ void ldsm_x4_t(uint32_t* r, unsigned addr) {
    asm volatile("ldmatrix.sync.aligned.m8n8.x4.trans.shared.b16 {%0,%1,%2,%3}, [%4];\n"
                 : "=r"(r[0]), "=r"(r[1]), "=r"(r[2]), "=r"(r[3]) : "r"(addr));
}
__device__ __forceinline__ void mma_f16(float* c, const uint32_t* a, uint32_t b0, uint32_t b1) {
    asm volatile("mma.sync.aligned.m16n8k16.row.col.f32.f16.f16.f32 "
                 "{%0,%1,%2,%3}, {%4,%5,%6,%7}, {%8,%9}, {%0,%1,%2,%3};\n"
                 : "+f"(c[0]), "+f"(c[1]), "+f"(c[2]), "+f"(c[3])
                 : "r"(a[0]), "r"(a[1]), "r"(a[2]), "r"(a[3]), "r"(b0), "r"(b1));
}
__device__ __forceinline__ void cp16(unsigned dst, const void* src) {
    asm volatile("cp.async.cg.shared.global [%0], [%1], 16;\n" :: "r"(dst), "l"(src));
}
__device__ __forceinline__ void cp16z(unsigned dst, const void* src, unsigned ssz) {
    asm volatile("cp.async.cg.shared.global [%0], [%1], 16, %2;\n"
                 :: "r"(dst), "l"(src), "r"(ssz));
}

// ---------------- zero kernels ----------------
__global__ void zero_pool_kernel(float* x, float* cnt, int M) {
    int total = M * CCH;
    for (int i = blockIdx.x * blockDim.x + threadIdx.x; i < total; i += gridDim.x * blockDim.x)
        x[i] = 0.f;
    for (int i = blockIdx.x * blockDim.x + threadIdx.x; i < M; i += gridDim.x * blockDim.x)
        cnt[i] = 0.f;
}
__global__ void zero_stats_kernel(float* stats) { stats[threadIdx.x] = 0.f; }

// ---------------- weight fp32 -> fp16 ----------------
__global__ void convert_w_kernel(const float* __restrict__ w, __half* __restrict__ wh, int n) {
    for (int i = blockIdx.x * blockDim.x + threadIdx.x; i < n; i += gridDim.x * blockDim.x)
        wh[i] = __float2half(w[i]);
}

// ---------------- encoder: warp-per-point Linear+LN+ReLU + segment-sum --------
__global__ __launch_bounds__(256)
void encode_pool_kernel(const float* __restrict__ gp,
                        const float* __restrict__ w_enc,
                        const float* __restrict__ b_enc,
                        const float* __restrict__ ln_g,
                        const float* __restrict__ ln_b,
                        const int*   __restrict__ inv_idx,
                        float* __restrict__ xsum,
                        float* __restrict__ cnt,
                        int Np) {
    const int lane = threadIdx.x & 31;
    const int gw = (blockIdx.x * blockDim.x + threadIdx.x) >> 5;
    const int nw = (gridDim.x * blockDim.x) >> 5;
    const int c0 = lane * 4;

    float wreg[14][4];
#pragma unroll
    for (int k = 0; k < 14; ++k) {
        float4 t = *(const float4*)(w_enc + k * CCH + c0);
        wreg[k][0] = t.x; wreg[k][1] = t.y; wreg[k][2] = t.z; wreg[k][3] = t.w;
    }
    float4 be = *(const float4*)(b_enc + c0);
    float4 lg = *(const float4*)(ln_g + c0);
    float4 lb = *(const float4*)(ln_b + c0);

    for (int i = gw; i < Np; i += nw) {
        float gv = (lane < 14) ? gp[(size_t)i * 14 + lane] : 0.f;
        float f0 = be.x, f1 = be.y, f2 = be.z, f3 = be.w;
#pragma unroll
        for (int k = 0; k < 14; ++k) {
            float s = __shfl_sync(0xffffffffu, gv, k);
            f0 += s * wreg[k][0]; f1 += s * wreg[k][1];
            f2 += s * wreg[k][2]; f3 += s * wreg[k][3];
        }
        float s1 = f0 + f1 + f2 + f3;
        float s2 = f0 * f0 + f1 * f1 + f2 * f2 + f3 * f3;
#pragma unroll
        for (int off = 16; off > 0; off >>= 1) {
            s1 += __shfl_xor_sync(0xffffffffu, s1, off);
            s2 += __shfl_xor_sync(0xffffffffu, s2, off);
        }
        float mu  = s1 * (1.f / 128.f);
        float inv = rsqrtf(s2 * (1.f / 128.f) - mu * mu + EPSV);
        int vox = inv_idx[i];
        float* dst = xsum + (size_t)vox * CCH + c0;
        atomicAdd(dst + 0, fmaxf((f0 - mu) * inv * lg.x + lb.x, 0.f));
        atomicAdd(dst + 1, fmaxf((f1 - mu) * inv * lg.y + lb.y, 0.f));
        atomicAdd(dst + 2, fmaxf((f2 - mu) * inv * lg.z + lb.z, 0.f));
        atomicAdd(dst + 3, fmaxf((f3 - mu) * inv * lg.w + lb.w, 0.f));
        if (lane == 0) atomicAdd(&cnt[vox], 1.f);
    }
}

// ---------------- pooled sums / counts -> fp32 + fp16 -------------------------
__global__ void pool_div_kernel(float* __restrict__ x, const float* __restrict__ cnt,
                                __half* __restrict__ xh, int M) {
    int total = M * CCH;
    for (int i = blockIdx.x * blockDim.x + threadIdx.x; i < total; i += gridDim.x * blockDim.x) {
        float v = x[i] / cnt[i >> 7];
        x[i] = v;
        xh[i] = __float2half(v);
    }
}

// ---------------- submanifold conv, fp16 mma.sync, cp.async double-buffered ---
// 256 voxels x 128 channels per 512-thread block (16 warps, 8(m) x 2(n) grid,
// 32x64 warp tiles). XOR-swizzled smem. One barrier per offset. BN sum/sumsq
// fused into the epilogue with warp-shuffle pre-reduction.
__global__ __launch_bounds__(512, 1)
void subm_conv_mma_kernel(const __half* __restrict__ xin,
                          const __half* __restrict__ W,   // 27 x 128 x 128 fp16
                          const int*   __restrict__ nbr_idx,
                          const float* __restrict__ nbr_mask,
                          float* __restrict__ y,
                          float* __restrict__ gstats,
                          int M) {
    extern __shared__ __align__(16) char smem_raw[];
    // layout: A0 @0 (64K), A1 @64K, B0 @128K, B1 @160K, sidx @192K
    int* sidx = (int*)(smem_raw + 2 * ATILE + 2 * BTILE);   // 27 x 256
    __shared__ int   s_act[27], s_sal[27], s_nact;
    __shared__ float sstat[CCH], ssq[CCH];

    const int tid  = threadIdx.x;
    const int warp = tid >> 5, lane = tid & 31;
    const int wm = warp >> 1;         // rows wm*32 .. +31  (0..7)
    const int wn = warp & 1;          // cols wn*64 .. +63
    const int v0 = blockIdx.x * BM;

    // ---- prologue: gather idx/mask, build active-offset list ----
    for (int j = tid; j < 27 * BM; j += 512) {
        int r = j / 27, o = j - r * 27;
        int v = v0 + r;
        int id = -1;
        if (v < M && nbr_mask[(size_t)v0 * 27 + j] != 0.f)
            id = nbr_idx[(size_t)v0 * 27 + j];
        sidx[o * BM + r] = id;
    }
    if (tid < 27) s_act[tid] = 0;
    if (tid < CCH) { sstat[tid] = 0.f; ssq[tid] = 0.f; }
    __syncthreads();
    if (warp < 8) {
#pragma unroll 1
        for (int o = 0; o < 27; ++o) {
            unsigned bal = __ballot_sync(0xffffffffu, sidx[o * BM + warp * 32 + lane] >= 0);
            if (lane == 0 && bal) s_act[o] = 1;
        }
    }
    __syncthreads();
    if (tid == 0) {
        int n = 0;
        for (int o = 0; o < 27; ++o) if (s_act[o]) s_sal[n++] = o;
        s_nact = n;
    }
    __syncthreads();
    const int nact = s_nact;

    const unsigned sAu = smem_u32(smem_raw);
    const unsigned sBu = sAu + 2 * ATILE;
    // A staging: thread -> (row 0..255, 8 chunks); B staging: (row 0..127, 4 chunks)
    const int arow = tid >> 1;
    const int ac0  = (tid & 1) * 8;
    const int brow = tid >> 2;
    const int bc0  = (tid & 3) * 4;

    float acc[2][8][4];
#pragma unroll
    for (int mi = 0; mi < 2; ++mi)
#pragma unroll
        for (int ni = 0; ni < 8; ++ni)
#pragma unroll
            for (int q = 0; q < 4; ++q) acc[mi][ni][q] = 0.f;

    // ---- stage offset 0 into buffer 0 ----
    {
        int o = s_sal[0];
        int id = sidx[o * BM + arow];
        unsigned ssz = (id >= 0) ? 16u : 0u;
        const __half* srcA = xin + (size_t)(id >= 0 ? id : 0) * CCH + ac0 * 8;
        const __half* srcB = W + (size_t)o * CCH * CCH + brow * CCH + bc0 * 8;
#pragma unroll
        for (int q = 0; q < 8; ++q)
            cp16z(sAu + swz(arow, ac0 + q), srcA + q * 8, ssz);
#pragma unroll
        for (int q = 0; q < 4; ++q)
            cp16 (sBu + swz(brow, bc0 + q), srcB + q * 8);
        asm volatile("cp.async.commit_group;\n" ::: "memory");
    }

    for (int t = 0; t < nact; ++t) {
        const int b = t & 1;
        asm volatile("cp.async.wait_group 0;\n" ::: "memory");
        __syncthreads();
        // stage t+1 into the other buffer (safe: all warps finished mma(t-1))
        if (t + 1 < nact) {
            int o = s_sal[t + 1];
            int id = sidx[o * BM + arow];
            unsigned ssz = (id >= 0) ? 16u : 0u;
            const __half* srcA = xin + (size_t)(id >= 0 ? id : 0) * CCH + ac0 * 8;
            const __half* srcB = W + (size_t)o * CCH * CCH + brow * CCH + bc0 * 8;
            unsigned dA = sAu + (unsigned)((b ^ 1) * ATILE);
            unsigned dB = sBu + (unsigned)((b ^ 1) * BTILE);
#pragma unroll
            for (int q = 0; q < 8; ++q)
                cp16z(dA + swz(arow, ac0 + q), srcA + q * 8, ssz);
#pragma unroll
            for (int q = 0; q < 4; ++q)
                cp16 (dB + swz(brow, bc0 + q), srcB + q * 8);
            asm volatile("cp.async.commit_group;\n" ::: "memory");
        }

        const unsigned Ab = sAu + (unsigned)(b * ATILE);
        const unsigned Bb = sBu + (unsigned)(b * BTILE);
#pragma unroll
        for (int kc = 0; kc < 8; ++kc) {
            uint32_t a[2][4];
#pragma unroll
            for (int mi = 0; mi < 2; ++mi) {
                int row = wm * 32 + mi * 16 + (lane & 15);
                ldsm_x4(a[mi], Ab + swz(row, kc * 2 + (lane >> 4)));
            }
#pragma unroll
            for (int nb = 0; nb < 4; ++nb) {
                uint32_t bb[4];
                int row = kc * 16 + (lane & 15);
                ldsm_x4_t(bb, Bb + swz(row, wn * 8 + nb * 2 + (lane >> 4)));
#pragma unroll
                for (int mi = 0; mi < 2; ++mi) {
                    mma_f16(acc[mi][nb * 2 + 0], a[mi], bb[0], bb[1]);
                    mma_f16(acc[mi][nb * 2 + 1], a[mi], bb[2], bb[3]);
                }
            }
        }
        __syncthreads();
    }

    // ---- epilogue: store y + fused BN partials (rows >= M are exact zeros) ----
    const int rbase = v0 + wm * 32 + (lane >> 2);
    const int cbase = wn * 64 + (lane & 3) * 2;
#pragma unroll
    for (int mi = 0; mi < 2; ++mi) {
#pragma unroll
        for (int ni = 0; ni < 8; ++ni) {
            int col = cbase + ni * 8;
            int r0 = rbase + mi * 16;
            if (r0 < M) {
                y[(size_t)r0 * CCH + col]     = acc[mi][ni][0];
                y[(size_t)r0 * CCH + col + 1] = acc[mi][ni][1];
            }
            int r1 = r0 + 8;
            if (r1 < M) {
                y[(size_t)r1 * CCH + col]     = acc[mi][ni][2];
                y[(size_t)r1 * CCH + col + 1] = acc[mi][ni][3];
            }
        }
    }
    // BN partials: reduce across the 8 lanes sharing a channel (lane bits 2..4),
    // then one smem atomic per channel from lanes 0..3.
#pragma unroll
    for (int ni = 0; ni < 8; ++ni) {
#pragma unroll
        for (int tt = 0; tt < 2; ++tt) {
            float a0 = acc[0][ni][tt],     a1 = acc[0][ni][2 + tt];
            float a2 = acc[1][ni][tt],     a3 = acc[1][ni][2 + tt];
            float s = a0 + a1 + a2 + a3;
            float q = a0 * a0 + a1 * a1 + a2 * a2 + a3 * a3;
#pragma unroll
            for (int off = 4; off <= 16; off <<= 1) {
                s += __shfl_xor_sync(0xffffffffu, s, off);
                q += __shfl_xor_sync(0xffffffffu, q, off);
            }
            if ((lane >> 2) == 0) {
                int c = cbase + ni * 8 + tt;
                atomicAdd(&sstat[c], s);
                atomicAdd(&ssq[c], q);
            }
        }
    }
    __syncthreads();
    if (tid < CCH) {
        atomicAdd(&gstats[tid],       sstat[tid]);
        atomicAdd(&gstats[CCH + tid], ssq[tid]);
    }
}

// ---------------- BN apply (+optional residual) + ReLU, fp32/fp16 out ---------
__global__ void bn_apply_kernel(const float* __restrict__ y,
                                const float* __restrict__ g,
                                const float* __restrict__ b,
                                const float* __restrict__ stats,
                                const float* __restrict__ residual,   // nullable
                                float* __restrict__ out_f32,          // nullable
                                __half* __restrict__ out_h16,         // nullable
                                int M) {
    int total = M * CCH;
    float invM = 1.f / (float)M;
    for (int i = blockIdx.x * blockDim.x + threadIdx.x; i < total; i += gridDim.x * blockDim.x) {
        int c = i & 127;
        float m   = stats[c] * invM;
        float var = stats[128 + c] * invM - m * m;
        float inv = rsqrtf(var + EPSV);
        float v = (y[i] - m) * inv * g[c] + b[c];
        if (residual) v += residual[i];
        v = fmaxf(v, 0.f);
        if (out_f32) out_f32[i] = v;
        if (out_h16) out_h16[i] = __float2half(v);
    }
}

// ---------------- head: gather + MLP(128->64->14) + residual add --------------
__global__ __launch_bounds__(128)
void head_kernel(const float* __restrict__ x,
                 const float* __restrict__ gp,
                 const int*   __restrict__ inv_idx,
                 const float* __restrict__ w1, const float* __restrict__ b1,
                 const float* __restrict__ w2, const float* __restrict__ b2,
                 float* __restrict__ out, int Np) {
    __shared__ float w1s[CCH * 64];
    __shared__ float w2s[64 * 14];
    __shared__ float b1s[64];
    __shared__ float b2s[14];
    __shared__ float pfs[2][CCH];
    __shared__ float hs[2][64];

    const int tid = threadIdx.x;
    for (int i = tid; i < CCH * 64; i += 128) w1s[i] = w1[i];
    for (int i = tid; i < 64 * 14; i += 128) w2s[i] = w2[i];
    if (tid < 64) b1s[tid] = b1[tid];
    if (tid < 14) b2s[tid] = b2[tid];
    __syncthreads();

    const int h = tid >> 6;
    const int j = tid & 63;

    for (int ip = blockIdx.x * 2; ip < Np; ip += gridDim.x * 2) {
        int i = ip + h;
        bool ok = (i < Np);
        if (ok) {
            int v = inv_idx[i];
            pfs[h][j]      = x[(size_t)v * CCH + j];
            pfs[h][j + 64] = x[(size_t)v * CCH + j + 64];
        }
        __syncthreads();
        if (ok) {
            float acc = b1s[j];
#pragma unroll 8
            for (int k = 0; k < CCH; ++k) acc += pfs[h][k] * w1s[k * 64 + j];
            hs[h][j] = fmaxf(acc, 0.f);
        }
        __syncthreads();
        if (ok && j < 14) {
            float d = b2s[j];
#pragma unroll
            for (int k = 0; k < 64; ++k) d += hs[h][k] * w2s[k * 14 + j];
            out[(size_t)i * 14 + j] = gp[(size_t)i * 14 + j] + d;
        }
        __syncthreads();
    }
}

// ---------------- launch -------------------------------------------------------
extern "C" void kernel_launch(void* const* d_in, const int* in_sizes, int n_in,
                              void* d_out, int out_size) {
    const float* gp       = (const float*)d_in[0];
    const float* w_enc    = (const float*)d_in[1];
    const float* b_enc    = (const float*)d_in[2];
    const float* ln_g     = (const float*)d_in[3];
    const float* ln_b     = (const float*)d_in[4];
    const float* conv_w   = (const float*)d_in[5];
    const float* bn_g     = (const float*)d_in[6];
    const float* bn_b     = (const float*)d_in[7];
    const float* w1       = (const float*)d_in[8];
    const float* b1       = (const float*)d_in[9];
    const float* w2       = (const float*)d_in[10];
    const float* b2       = (const float*)d_in[11];
    const float* nbr_mask = (const float*)d_in[12];
    const int*   inv_idx  = (const int*)d_in[13];
    const int*   nbr_idx  = (const int*)d_in[14];
    float* out = (float*)d_out;

    const int Np = in_sizes[0] / 14;
    const int M  = in_sizes[12] / 27;

    float *px, *py, *pcnt, *pstats;
    __half *pxh, *pah, *pwh;
    cudaGetSymbolAddress((void**)&px,     g_x);
    cudaGetSymbolAddress((void**)&py,     g_y);
    cudaGetSymbolAddress((void**)&pxh,    g_xh);
    cudaGetSymbolAddress((void**)&pah,    g_ah);
    cudaGetSymbolAddress((void**)&pwh,    g_wh);
    cudaGetSymbolAddress((void**)&pcnt,   g_cnt);
    cudaGetSymbolAddress((void**)&pstats, g_stats);

    const int CONV_SMEM = 2 * ATILE + 2 * BTILE + 27 * BM * 4;  // 196608+27648=224256
    cudaFuncSetAttribute(subm_conv_mma_kernel,
                         cudaFuncAttributeMaxDynamicSharedMemorySize, CONV_SMEM);

    convert_w_kernel<<<1024, 256>>>(conv_w, pwh, 4 * 27 * CCH * CCH);
    zero_pool_kernel<<<1024, 256>>>(px, pcnt, M);
    encode_pool_kernel<<<512, 256>>>(gp, w_enc, b_enc, ln_g, ln_b, inv_idx, px, pcnt, Np);
    pool_div_kernel<<<2048, 256>>>(px, pcnt, pxh, M);

    const int tiles = (M + BM - 1) / BM;
    for (int blk = 0; blk < 2; ++blk) {
        const int l0 = 2 * blk, l1 = 2 * blk + 1;
        // conv1 (fused BN stats) -> BN apply -> ReLU (fp16 out)
        zero_stats_kernel<<<1, 256>>>(pstats);
        subm_conv_mma_kernel<<<tiles, 512, CONV_SMEM>>>(
            pxh, pwh + (size_t)l0 * 27 * CCH * CCH, nbr_idx, nbr_mask, py, pstats, M);
        bn_apply_kernel<<<2048, 256>>>(py, bn_g + l0 * CCH, bn_b + l0 * CCH, pstats,
                                       (const float*)0, (float*)0, pah, M);
        // conv2 (fused BN stats) -> BN apply + residual -> ReLU (fp32 + fp16)
        zero_stats_kernel<<<1, 256>>>(pstats);
        subm_conv_mma_kernel<<<tiles, 512, CONV_SMEM>>>(
            pah, pwh + (size_t)l1 * 27 * CCH * CCH, nbr_idx, nbr_mask, py, pstats, M);
        bn_apply_kernel<<<2048, 256>>>(py, bn_g + l1 * CCH, bn_b + l1 * CCH, pstats,
                                       px, px, pxh, M);
    }

    head_kernel<<<2048, 128>>>(px, gp, inv_idx, w1, b1, w2, b2, out, Np);
}

// round 8
// speedup vs baseline: 1.5463x; 1.1146x over previous
#include <cuda_runtime.h>
#include <cuda_fp16.h>
#include <stdint.h>
#include <math.h>

#define NPTS 200000
#define CCH  128
#define EPSV 1e-5f
#define ATILE 65536u            // 256 x 128 halfs, swizzled
#define BTILE 32768u            // 128 x 128 halfs, swizzled
#define BM    256

// ---------------- scratch (device globals; no allocations anywhere) ----------
__device__ float  g_x[NPTS * CCH];           // fp32 pooled feats / residual
__device__ float  g_y[NPTS * CCH];           // fp32 conv output / dvox
__device__ __half g_xh[NPTS * CCH];          // fp16 conv input (x path)
__device__ __half g_ah[NPTS * CCH];          // fp16 conv input (mid path)
__device__ __half g_wh[4 * 27 * CCH * CCH];  // fp16 conv weights
__device__ __half g_w1h[CCH * 64];           // fp16 head weights
__device__ float  g_cnt[NPTS];
__device__ float  g_stats[256];              // [0..127]=sum [128..255]=sumsq

// ---------------- helpers ----------------
__device__ __forceinline__ unsigned smem_u32(const void* p) {
    return (unsigned)__cvta_generic_to_shared(p);
}
// swizzled byte offset, 256B rows (128 halfs): 16 chunks of 16B, chunk ^= row&7
__device__ __forceinline__ unsigned swz(int row, int c16) {
    return (unsigned)(row * 256 + (((c16) ^ (row & 7)) << 4));
}
// swizzled byte offset, 128B rows (64 halfs): 8 chunks of 16B
__device__ __forceinline__ unsigned swz64(int row, int c16) {
    return (unsigned)(row * 128 + (((c16) ^ (row & 7)) << 4));
}
__device__ __forceinline__ void ldsm_x4(uint32_t* r, unsigned addr) {
    asm volatile("ldmatrix.sync.aligned.m8n8.x4.shared.b16 {%0,%1,%2,%3}, [%4];\n"
                 : "=r"(r[0]), "=r"(r[1]), "=r"(r[2]), "=r"(r[3]) : "r"(addr));
}
__device__ __forceinline__ void ldsm_x4_t(uint32_t* r, unsigned addr) {
    asm volatile("ldmatrix.sync.aligned.m8n8.x4.trans.shared.b16 {%0,%1,%2,%3}, [%4];\n"
                 : "=r"(r[0]), "=r"(r[1]), "=r"(r[2]), "=r"(r[3]) : "r"(addr));
}
__device__ __forceinline__ void mma_f16(float* c, const uint32_t* a, uint32_t b0, uint32_t b1) {
    asm volatile("mma.sync.aligned.m16n8k16.row.col.f32.f16.f16.f32 "
                 "{%0,%1,%2,%3}, {%4,%5,%6,%7}, {%8,%9}, {%0,%1,%2,%3};\n"
                 : "+f"(c[0]), "+f"(c[1]), "+f"(c[2]), "+f"(c[3])
                 : "r"(a[0]), "r"(a[1]), "r"(a[2]), "r"(a[3]), "r"(b0), "r"(b1));
}
__device__ __forceinline__ void cp16(unsigned dst, const void* src) {
    asm volatile("cp.async.cg.shared.global [%0], [%1], 16;\n" :: "r"(dst), "l"(src));
}
__device__ __forceinline__ void cp16z(unsigned dst, const void* src, unsigned ssz) {
    asm volatile("cp.async.cg.shared.global [%0], [%1], 16, %2;\n"
                 :: "r"(dst), "l"(src), "r"(ssz));
}

// ---------------- weight fp32 -> fp16 ----------------
__global__ void convert_w_kernel(const float* __restrict__ w, __half* __restrict__ wh, int n) {
    for (int i = blockIdx.x * blockDim.x + threadIdx.x; i < n; i += gridDim.x * blockDim.x)
        wh[i] = __float2half(w[i]);
}

// ---------------- encoder: warp-per-point Linear+LN+ReLU + segment-sum --------
__global__ __launch_bounds__(256)
void encode_pool_kernel(const float* __restrict__ gp,
                        const float* __restrict__ w_enc,
                        const float* __restrict__ b_enc,
                        const float* __restrict__ ln_g,
                        const float* __restrict__ ln_b,
                        const int*   __restrict__ inv_idx,
                        float* __restrict__ xsum,
                        float* __restrict__ cnt,
                        int Np) {
    const int lane = threadIdx.x & 31;
    const int gw = (blockIdx.x * blockDim.x + threadIdx.x) >> 5;
    const int nw = (gridDim.x * blockDim.x) >> 5;
    const int c0 = lane * 4;

    float wreg[14][4];
#pragma unroll
    for (int k = 0; k < 14; ++k) {
        float4 t = *(const float4*)(w_enc + k * CCH + c0);
        wreg[k][0] = t.x; wreg[k][1] = t.y; wreg[k][2] = t.z; wreg[k][3] = t.w;
    }
    float4 be = *(const float4*)(b_enc + c0);
    float4 lg = *(const float4*)(ln_g + c0);
    float4 lb = *(const float4*)(ln_b + c0);

    for (int i = gw; i < Np; i += nw) {
        float gv = (lane < 14) ? gp[(size_t)i * 14 + lane] : 0.f;
        float f0 = be.x, f1 = be.y, f2 = be.z, f3 = be.w;
#pragma unroll
        for (int k = 0; k < 14; ++k) {
            float s = __shfl_sync(0xffffffffu, gv, k);
            f0 += s * wreg[k][0]; f1 += s * wreg[k][1];
            f2 += s * wreg[k][2]; f3 += s * wreg[k][3];
        }
        float s1 = f0 + f1 + f2 + f3;
        float s2 = f0 * f0 + f1 * f1 + f2 * f2 + f3 * f3;
#pragma unroll
        for (int off = 16; off > 0; off >>= 1) {
            s1 += __shfl_xor_sync(0xffffffffu, s1, off);
            s2 += __shfl_xor_sync(0xffffffffu, s2, off);
        }
        float mu  = s1 * (1.f / 128.f);
        float inv = rsqrtf(s2 * (1.f / 128.f) - mu * mu + EPSV);
        int vox = inv_idx[i];
        float* dst = xsum + (size_t)vox * CCH + c0;
        atomicAdd(dst + 0, fmaxf((f0 - mu) * inv * lg.x + lb.x, 0.f));
        atomicAdd(dst + 1, fmaxf((f1 - mu) * inv * lg.y + lb.y, 0.f));
        atomicAdd(dst + 2, fmaxf((f2 - mu) * inv * lg.z + lb.z, 0.f));
        atomicAdd(dst + 3, fmaxf((f3 - mu) * inv * lg.w + lb.w, 0.f));
        if (lane == 0) atomicAdd(&cnt[vox], 1.f);
    }
}

// ---------------- pooled sums / counts -> fp32 + fp16 -------------------------
__global__ void pool_div_kernel(float* __restrict__ x, const float* __restrict__ cnt,
                                __half* __restrict__ xh, int M) {
    int total = M * CCH;
    for (int i = blockIdx.x * blockDim.x + threadIdx.x; i < total; i += gridDim.x * blockDim.x) {
        float v = x[i] / cnt[i >> 7];
        x[i] = v;
        xh[i] = __float2half(v);
    }
}

// ---------------- submanifold conv, fp16 mma.sync, cp.async double-buffered ---
__global__ __launch_bounds__(512, 1)
void subm_conv_mma_kernel(const __half* __restrict__ xin,
                          const __half* __restrict__ W,   // 27 x 128 x 128 fp16
                          const int*   __restrict__ nbr_idx,
                          const float* __restrict__ nbr_mask,
                          float* __restrict__ y,
                          float* __restrict__ gstats,
                          int M) {
    extern __shared__ __align__(16) char smem_raw[];
    int* sidx = (int*)(smem_raw + 2 * ATILE + 2 * BTILE);   // 27 x 256
    __shared__ int   s_act[27], s_sal[27], s_nact;
    __shared__ float sstat[CCH], ssq[CCH];

    const int tid  = threadIdx.x;
    const int warp = tid >> 5, lane = tid & 31;
    const int wm = warp >> 1;
    const int wn = warp & 1;
    const int v0 = blockIdx.x * BM;

    for (int j = tid; j < 27 * BM; j += 512) {
        int r = j / 27, o = j - r * 27;
        int v = v0 + r;
        int id = -1;
        if (v < M && nbr_mask[(size_t)v0 * 27 + j] != 0.f)
            id = nbr_idx[(size_t)v0 * 27 + j];
        sidx[o * BM + r] = id;
    }
    if (tid < 27) s_act[tid] = 0;
    if (tid < CCH) { sstat[tid] = 0.f; ssq[tid] = 0.f; }
    __syncthreads();
    if (warp < 8) {
#pragma unroll 1
        for (int o = 0; o < 27; ++o) {
            unsigned bal = __ballot_sync(0xffffffffu, sidx[o * BM + warp * 32 + lane] >= 0);
            if (lane == 0 && bal) s_act[o] = 1;
        }
    }
    __syncthreads();
    if (tid == 0) {
        int n = 0;
        for (int o = 0; o < 27; ++o) if (s_act[o]) s_sal[n++] = o;
        s_nact = n;
    }
    __syncthreads();
    const int nact = s_nact;

    const unsigned sAu = smem_u32(smem_raw);
    const unsigned sBu = sAu + 2 * ATILE;
    const int arow = tid >> 1;
    const int ac0  = (tid & 1) * 8;
    const int brow = tid >> 2;
    const int bc0  = (tid & 3) * 4;

    float acc[2][8][4];
#pragma unroll
    for (int mi = 0; mi < 2; ++mi)
#pragma unroll
        for (int ni = 0; ni < 8; ++ni)
#pragma unroll
            for (int q = 0; q < 4; ++q) acc[mi][ni][q] = 0.f;

    {
        int o = s_sal[0];
        int id = sidx[o * BM + arow];
        unsigned ssz = (id >= 0) ? 16u : 0u;
        const __half* srcA = xin + (size_t)(id >= 0 ? id : 0) * CCH + ac0 * 8;
        const __half* srcB = W + (size_t)o * CCH * CCH + brow * CCH + bc0 * 8;
#pragma unroll
        for (int q = 0; q < 8; ++q)
            cp16z(sAu + swz(arow, ac0 + q), srcA + q * 8, ssz);
#pragma unroll
        for (int q = 0; q < 4; ++q)
            cp16 (sBu + swz(brow, bc0 + q), srcB + q * 8);
        asm volatile("cp.async.commit_group;\n" ::: "memory");
    }

    for (int t = 0; t < nact; ++t) {
        const int b = t & 1;
        asm volatile("cp.async.wait_group 0;\n" ::: "memory");
        __syncthreads();
        if (t + 1 < nact) {
            int o = s_sal[t + 1];
            int id = sidx[o * BM + arow];
            unsigned ssz = (id >= 0) ? 16u : 0u;
            const __half* srcA = xin + (size_t)(id >= 0 ? id : 0) * CCH + ac0 * 8;
            const __half* srcB = W + (size_t)o * CCH * CCH + brow * CCH + bc0 * 8;
            unsigned dA = sAu + (unsigned)((b ^ 1) * ATILE);
            unsigned dB = sBu + (unsigned)((b ^ 1) * BTILE);
#pragma unroll
            for (int q = 0; q < 8; ++q)
                cp16z(dA + swz(arow, ac0 + q), srcA + q * 8, ssz);
#pragma unroll
            for (int q = 0; q < 4; ++q)
                cp16 (dB + swz(brow, bc0 + q), srcB + q * 8);
            asm volatile("cp.async.commit_group;\n" ::: "memory");
        }

        const unsigned Ab = sAu + (unsigned)(b * ATILE);
        const unsigned Bb = sBu + (unsigned)(b * BTILE);
#pragma unroll
        for (int kc = 0; kc < 8; ++kc) {
            uint32_t a[2][4];
#pragma unroll
            for (int mi = 0; mi < 2; ++mi) {
                int row = wm * 32 + mi * 16 + (lane & 15);
                ldsm_x4(a[mi], Ab + swz(row, kc * 2 + (lane >> 4)));
            }
#pragma unroll
            for (int nb = 0; nb < 4; ++nb) {
                uint32_t bb[4];
                int row = kc * 16 + (lane & 15);
                ldsm_x4_t(bb, Bb + swz(row, wn * 8 + nb * 2 + (lane >> 4)));
#pragma unroll
                for (int mi = 0; mi < 2; ++mi) {
                    mma_f16(acc[mi][nb * 2 + 0], a[mi], bb[0], bb[1]);
                    mma_f16(acc[mi][nb * 2 + 1], a[mi], bb[2], bb[3]);
                }
            }
        }
        __syncthreads();
    }

    const int rbase = v0 + wm * 32 + (lane >> 2);
    const int cbase = wn * 64 + (lane & 3) * 2;
#pragma unroll
    for (int mi = 0; mi < 2; ++mi) {
#pragma unroll
        for (int ni = 0; ni < 8; ++ni) {
            int col = cbase + ni * 8;
            int r0 = rbase + mi * 16;
            if (r0 < M) {
                y[(size_t)r0 * CCH + col]     = acc[mi][ni][0];
                y[(size_t)r0 * CCH + col + 1] = acc[mi][ni][1];
            }
            int r1 = r0 + 8;
            if (r1 < M) {
                y[(size_t)r1 * CCH + col]     = acc[mi][ni][2];
                y[(size_t)r1 * CCH + col + 1] = acc[mi][ni][3];
            }
        }
    }
#pragma unroll
    for (int ni = 0; ni < 8; ++ni) {
#pragma unroll
        for (int tt = 0; tt < 2; ++tt) {
            float a0 = acc[0][ni][tt],     a1 = acc[0][ni][2 + tt];
            float a2 = acc[1][ni][tt],     a3 = acc[1][ni][2 + tt];
            float s = a0 + a1 + a2 + a3;
            float q = a0 * a0 + a1 * a1 + a2 * a2 + a3 * a3;
#pragma unroll
            for (int off = 4; off <= 16; off <<= 1) {
                s += __shfl_xor_sync(0xffffffffu, s, off);
                q += __shfl_xor_sync(0xffffffffu, q, off);
            }
            if ((lane >> 2) == 0) {
                int c = cbase + ni * 8 + tt;
                atomicAdd(&sstat[c], s);
                atomicAdd(&ssq[c], q);
            }
        }
    }
    __syncthreads();
    if (tid < CCH) {
        atomicAdd(&gstats[tid],       sstat[tid]);
        atomicAdd(&gstats[CCH + tid], ssq[tid]);
    }
}

// ---------------- BN apply (+optional residual) + ReLU, vectorized ------------
__global__ void bn_apply_kernel(const float* __restrict__ y,
                                const float* __restrict__ g,
                                const float* __restrict__ b,
                                const float* __restrict__ stats,
                                const float* __restrict__ residual,   // nullable
                                float* __restrict__ out_f32,          // nullable
                                __half* __restrict__ out_h16,         // nullable
                                int M) {
    int total4 = M * 32;
    float invM = 1.f / (float)M;
    for (int i = blockIdx.x * blockDim.x + threadIdx.x; i < total4; i += gridDim.x * blockDim.x) {
        int c0 = (i & 31) * 4;
        float4 yv = ((const float4*)y)[i];
        float v[4] = {yv.x, yv.y, yv.z, yv.w};
#pragma unroll
        for (int q = 0; q < 4; ++q) {
            int c = c0 + q;
            float m   = stats[c] * invM;
            float var = stats[128 + c] * invM - m * m;
            float inv = rsqrtf(var + EPSV);
            v[q] = (v[q] - m) * inv * g[c] + b[c];
        }
        if (residual) {
            float4 rv = ((const float4*)residual)[i];
            v[0] += rv.x; v[1] += rv.y; v[2] += rv.z; v[3] += rv.w;
        }
#pragma unroll
        for (int q = 0; q < 4; ++q) v[q] = fmaxf(v[q], 0.f);
        if (out_f32) ((float4*)out_f32)[i] = make_float4(v[0], v[1], v[2], v[3]);
        if (out_h16) {
            ((__half2*)out_h16)[2 * i]     = __floats2half2_rn(v[0], v[1]);
            ((__half2*)out_h16)[2 * i + 1] = __floats2half2_rn(v[2], v[3]);
        }
    }
}

// ---------------- head on voxels: dvox = relu(x@w1+b1)@w2 + b2 ----------------
// 128 voxels per 256-thread CTA (8 warps, each computes 16 rows x 64 cols).
__global__ __launch_bounds__(256)
void head_vox_kernel(const __half* __restrict__ xh,
                     const __half* __restrict__ w1h,   // [128 x 64] fp16
                     const float* __restrict__ b1,
                     const float* __restrict__ w2,     // [64 x 14] fp32
                     const float* __restrict__ b2,
                     float* __restrict__ dvox,         // [M x 14]
                     int M) {
    extern __shared__ __align__(16) char smem_raw[];
    // A tile 32KB @0, w1 tile 16KB @32K, hs [128][65] fp32 @48K
    float* hs = (float*)(smem_raw + 49152);
    __shared__ float b1s[64], b2s[14], w2s[64 * 14];

    const int tid  = threadIdx.x;
    const int warp = tid >> 5, lane = tid & 31;
    const int v0 = blockIdx.x * 128;

    const unsigned sAu = smem_u32(smem_raw);
    const unsigned sBu = sAu + 32768u;

    // stage A (voxel rows) + w1
    {
        int row = tid >> 1, c0 = (tid & 1) * 8;
        unsigned ssz = (v0 + row < M) ? 16u : 0u;
        const __half* srcA = xh + (size_t)(v0 + row < M ? v0 + row : 0) * CCH + c0 * 8;
#pragma unroll
        for (int q = 0; q < 8; ++q)
            cp16z(sAu + swz(row, c0 + q), srcA + q * 8, ssz);
    }
    for (int j = tid; j < 1024; j += 256) {
        int row = j >> 3, c = j & 7;
        cp16(sBu + swz64(row, c), w1h + row * 64 + c * 8);
    }
    asm volatile("cp.async.commit_group;\n" ::: "memory");
    if (tid < 64) b1s[tid] = b1[tid];
    if (tid < 14) b2s[tid] = b2[tid];
    for (int j = tid; j < 64 * 14; j += 256) w2s[j] = w2[j];
    asm volatile("cp.async.wait_group 0;\n" ::: "memory");
    __syncthreads();

    // GEMM: each warp rows warp*16..+15, all 64 cols
    float acc[8][4];
#pragma unroll
    for (int ni = 0; ni < 8; ++ni)
#pragma unroll
        for (int q = 0; q < 4; ++q) acc[ni][q] = 0.f;
#pragma unroll
    for (int kc = 0; kc < 8; ++kc) {
        uint32_t a[4];
        ldsm_x4(a, sAu + swz(warp * 16 + (lane & 15), kc * 2 + (lane >> 4)));
#pragma unroll
        for (int nb = 0; nb < 4; ++nb) {
            uint32_t bb[4];
            ldsm_x4_t(bb, sBu + swz64(kc * 16 + (lane & 15), nb * 2 + (lane >> 4)));
            mma_f16(acc[nb * 2 + 0], a, bb[0], bb[1]);
            mma_f16(acc[nb * 2 + 1], a, bb[2], bb[3]);
        }
    }
    // h = relu(acc + b1) -> smem [128][65]
    {
        int r0 = warp * 16 + (lane >> 2);
        int c0 = (lane & 3) * 2;
#pragma unroll
        for (int ni = 0; ni < 8; ++ni) {
            int c = c0 + ni * 8;
            hs[r0 * 65 + c]           = fmaxf(acc[ni][0] + b1s[c], 0.f);
            hs[r0 * 65 + c + 1]       = fmaxf(acc[ni][1] + b1s[c + 1], 0.f);
            hs[(r0 + 8) * 65 + c]     = fmaxf(acc[ni][2] + b1s[c], 0.f);
            hs[(r0 + 8) * 65 + c + 1] = fmaxf(acc[ni][3] + b1s[c + 1], 0.f);
        }
    }
    __syncthreads();

    // phase 2: h[128x64] @ w2[64x14] + b2 -> dvox
    {
        int r = tid >> 1;
        int cb = (tid & 1) * 7;          // cols cb..cb+6
        if (v0 + r < M) {
            float d[7];
#pragma unroll
            for (int c = 0; c < 7; ++c) d[c] = b2s[cb + c];
#pragma unroll 8
            for (int k = 0; k < 64; ++k) {
                float hv = hs[r * 65 + k];
#pragma unroll
                for (int c = 0; c < 7; ++c) d[c] += hv * w2s[k * 14 + cb + c];
            }
            float* dst = dvox + (size_t)(v0 + r) * 14 + cb;
#pragma unroll
            for (int c = 0; c < 7; ++c) dst[c] = d[c];
        }
    }
}

// ---------------- scatter: out = gp + dvox[inv_idx] ---------------------------
__global__ void scatter_out_kernel(const float* __restrict__ gp,
                                   const float* __restrict__ dvox,
                                   const int*   __restrict__ inv_idx,
                                   float* __restrict__ out, int Np) {
    int total = Np * 14;
    for (int t = blockIdx.x * blockDim.x + threadIdx.x; t < total; t += gridDim.x * blockDim.x) {
        int i = t / 14, j = t - i * 14;
        out[t] = gp[t] + dvox[(size_t)inv_idx[i] * 14 + j];
    }
}

// ---------------- launch -------------------------------------------------------
extern "C" void kernel_launch(void* const* d_in, const int* in_sizes, int n_in,
                              void* d_out, int out_size) {
    const float* gp       = (const float*)d_in[0];
    const float* w_enc    = (const float*)d_in[1];
    const float* b_enc    = (const float*)d_in[2];
    const float* ln_g     = (const float*)d_in[3];
    const float* ln_b     = (const float*)d_in[4];
    const float* conv_w   = (const float*)d_in[5];
    const float* bn_g     = (const float*)d_in[6];
    const float* bn_b     = (const float*)d_in[7];
    const float* w1       = (const float*)d_in[8];
    const float* b1       = (const float*)d_in[9];
    const float* w2       = (const float*)d_in[10];
    const float* b2       = (const float*)d_in[11];
    const float* nbr_mask = (const float*)d_in[12];
    const int*   inv_idx  = (const int*)d_in[13];
    const int*   nbr_idx  = (const int*)d_in[14];
    float* out = (float*)d_out;

    const int Np = in_sizes[0] / 14;
    const int M  = in_sizes[12] / 27;

    float *px, *py, *pcnt, *pstats;
    __half *pxh, *pah, *pwh, *pw1h;
    cudaGetSymbolAddress((void**)&px,     g_x);
    cudaGetSymbolAddress((void**)&py,     g_y);
    cudaGetSymbolAddress((void**)&pxh,    g_xh);
    cudaGetSymbolAddress((void**)&pah,    g_ah);
    cudaGetSymbolAddress((void**)&pwh,    g_wh);
    cudaGetSymbolAddress((void**)&pw1h,   g_w1h);
    cudaGetSymbolAddress((void**)&pcnt,   g_cnt);
    cudaGetSymbolAddress((void**)&pstats, g_stats);

    const int CONV_SMEM = 2 * ATILE + 2 * BTILE + 27 * BM * 4;  // 224256
    cudaFuncSetAttribute(subm_conv_mma_kernel,
                         cudaFuncAttributeMaxDynamicSharedMemorySize, CONV_SMEM);
    const int HEAD_SMEM = 49152 + 128 * 65 * 4;                 // 82432
    cudaFuncSetAttribute(head_vox_kernel,
                         cudaFuncAttributeMaxDynamicSharedMemorySize, HEAD_SMEM);

    convert_w_kernel<<<1024, 256>>>(conv_w, pwh, 4 * 27 * CCH * CCH);
    convert_w_kernel<<<8, 256>>>(w1, pw1h, CCH * 64);
    cudaMemsetAsync(px, 0, (size_t)M * CCH * sizeof(float));
    cudaMemsetAsync(pcnt, 0, (size_t)M * sizeof(float));
    encode_pool_kernel<<<512, 256>>>(gp, w_enc, b_enc, ln_g, ln_b, inv_idx, px, pcnt, Np);
    pool_div_kernel<<<2048, 256>>>(px, pcnt, pxh, M);

    const int tiles = (M + BM - 1) / BM;
    for (int blk = 0; blk < 2; ++blk) {
        const int l0 = 2 * blk, l1 = 2 * blk + 1;
        // conv1 (fused BN stats) -> BN apply -> ReLU (fp16 out)
        cudaMemsetAsync(pstats, 0, 256 * sizeof(float));
        subm_conv_mma_kernel<<<tiles, 512, CONV_SMEM>>>(
            pxh, pwh + (size_t)l0 * 27 * CCH * CCH, nbr_idx, nbr_mask, py, pstats, M);
        bn_apply_kernel<<<2048, 256>>>(py, bn_g + l0 * CCH, bn_b + l0 * CCH, pstats,
                                       (const float*)0, (float*)0, pah, M);
        // conv2 (fused BN stats) -> BN apply + residual -> ReLU
        cudaMemsetAsync(pstats, 0, 256 * sizeof(float));
        subm_conv_mma_kernel<<<tiles, 512, CONV_SMEM>>>(
            pah, pwh + (size_t)l1 * 27 * CCH * CCH, nbr_idx, nbr_mask, py, pstats, M);
        if (blk == 0) {
            // write fp32 residual for block 2 + fp16 conv input
            bn_apply_kernel<<<2048, 256>>>(py, bn_g + l1 * CCH, bn_b + l1 * CCH, pstats,
                                           px, px, pxh, M);
        } else {
            // final: only fp16 needed (head consumes fp16)
            bn_apply_kernel<<<2048, 256>>>(py, bn_g + l1 * CCH, bn_b + l1 * CCH, pstats,
                                           px, (float*)0, pxh, M);
        }
    }

    head_vox_kernel<<<(M + 127) / 128, 256, HEAD_SMEM>>>(pxh, pw1h, b1, w2, b2, py, M);
    scatter_out_kernel<<<2048, 256>>>(gp, py, inv_idx, out, Np);
}

// round 9
// speedup vs baseline: 1.6795x; 1.0862x over previous
#include <cuda_runtime.h>
#include <cuda_fp16.h>
#include <stdint.h>
#include <math.h>

#define NPTS 200000
#define CCH  128
#define EPSV 1e-5f
#define ATILE 65536u            // 256 x 128 halfs, swizzled
#define BTILE 32768u            // 128 x 128 halfs, swizzled
#define BM    256

// ---------------- scratch (device globals; no allocations anywhere) ----------
__device__ float  g_x[NPTS * CCH];           // fp32 pooled feats / residual
__device__ float  g_y[NPTS * CCH];           // fp32 conv output / dvox
__device__ __half g_xh[NPTS * CCH];          // fp16 conv input (x path)
__device__ __half g_ah[NPTS * CCH];          // fp16 conv input (mid path)
__device__ __half g_wh[4 * 27 * CCH * CCH];  // fp16 conv weights
__device__ __half g_w1h[CCH * 64];           // fp16 head weights
__device__ float  g_cnt[NPTS];
__device__ float  g_stats[256];              // [0..127]=sum [128..255]=sumsq

// ---------------- helpers ----------------
__device__ __forceinline__ unsigned smem_u32(const void* p) {
    return (unsigned)__cvta_generic_to_shared(p);
}
__device__ __forceinline__ unsigned swz(int row, int c16) {
    return (unsigned)(row * 256 + (((c16) ^ (row & 7)) << 4));
}
__device__ __forceinline__ unsigned swz64(int row, int c16) {
    return (unsigned)(row * 128 + (((c16) ^ (row & 7)) << 4));
}
__device__ __forceinline__ void ldsm_x4(uint32_t* r, unsigned addr) {
    asm volatile("ldmatrix.sync.aligned.m8n8.x4.shared.b16 {%0,%1,%2,%3}, [%4];\n"
                 : "=r"(r[0]), "=r"(r[1]), "=r"(r[2]), "=r"(r[3]) : "r"(addr));
}
__device__ __forceinline__ void ldsm_x4_t(uint32_t* r, unsigned addr) {
    asm volatile("ldmatrix.sync.aligned.m8n8.x4.trans.shared.b16 {%0,%1,%2,%3}, [%4];\n"
                 : "=r"(r[0]), "=r"(r[1]), "=r"(r[2]), "=r"(r[3]) : "r"(addr));
}
__device__ __forceinline__ void mma_f16(float* c, const uint32_t* a, uint32_t b0, uint32_t b1) {
    asm volatile("mma.sync.aligned.m16n8k16.row.col.f32.f16.f16.f32 "
                 "{%0,%1,%2,%3}, {%4,%5,%6,%7}, {%8,%9}, {%0,%1,%2,%3};\n"
                 : "+f"(c[0]), "+f"(c[1]), "+f"(c[2]), "+f"(c[3])
                 : "r"(a[0]), "r"(a[1]), "r"(a[2]), "r"(a[3]), "r"(b0), "r"(b1));
}
__device__ __forceinline__ void cp16(unsigned dst, const void* src) {
    asm volatile("cp.async.cg.shared.global [%0], [%1], 16;\n" :: "r"(dst), "l"(src));
}
__device__ __forceinline__ void cp16z(unsigned dst, const void* src, unsigned ssz) {
    asm volatile("cp.async.cg.shared.global [%0], [%1], 16, %2;\n"
                 :: "r"(dst), "l"(src), "r"(ssz));
}

// ---------------- weight fp32 -> fp16 ----------------
__global__ void convert_w_kernel(const float* __restrict__ w, __half* __restrict__ wh, int n) {
    for (int i = blockIdx.x * blockDim.x + threadIdx.x; i < n; i += gridDim.x * blockDim.x)
        wh[i] = __float2half(w[i]);
}

// ---------------- encoder: warp-per-point Linear+LN+ReLU + segment-sum --------
__global__ __launch_bounds__(256)
void encode_pool_kernel(const float* __restrict__ gp,
                        const float* __restrict__ w_enc,
                        const float* __restrict__ b_enc,
                        const float* __restrict__ ln_g,
                        const float* __restrict__ ln_b,
                        const int*   __restrict__ inv_idx,
                        float* __restrict__ xsum,
                        float* __restrict__ cnt,
                        int Np) {
    const int lane = threadIdx.x & 31;
    const int gw = (blockIdx.x * blockDim.x + threadIdx.x) >> 5;
    const int nw = (gridDim.x * blockDim.x) >> 5;
    const int c0 = lane * 4;

    float wreg[14][4];
#pragma unroll
    for (int k = 0; k < 14; ++k) {
        float4 t = *(const float4*)(w_enc + k * CCH + c0);
        wreg[k][0] = t.x; wreg[k][1] = t.y; wreg[k][2] = t.z; wreg[k][3] = t.w;
    }
    float4 be = *(const float4*)(b_enc + c0);
    float4 lg = *(const float4*)(ln_g + c0);
    float4 lb = *(const float4*)(ln_b + c0);

    for (int i = gw; i < Np; i += nw) {
        float gv = (lane < 14) ? gp[(size_t)i * 14 + lane] : 0.f;
        float f0 = be.x, f1 = be.y, f2 = be.z, f3 = be.w;
#pragma unroll
        for (int k = 0; k < 14; ++k) {
            float s = __shfl_sync(0xffffffffu, gv, k);
            f0 += s * wreg[k][0]; f1 += s * wreg[k][1];
            f2 += s * wreg[k][2]; f3 += s * wreg[k][3];
        }
        float s1 = f0 + f1 + f2 + f3;
        float s2 = f0 * f0 + f1 * f1 + f2 * f2 + f3 * f3;
#pragma unroll
        for (int off = 16; off > 0; off >>= 1) {
            s1 += __shfl_xor_sync(0xffffffffu, s1, off);
            s2 += __shfl_xor_sync(0xffffffffu, s2, off);
        }
        float mu  = s1 * (1.f / 128.f);
        float inv = rsqrtf(s2 * (1.f / 128.f) - mu * mu + EPSV);
        int vox = inv_idx[i];
        float* dst = xsum + (size_t)vox * CCH + c0;
        atomicAdd(dst + 0, fmaxf((f0 - mu) * inv * lg.x + lb.x, 0.f));
        atomicAdd(dst + 1, fmaxf((f1 - mu) * inv * lg.y + lb.y, 0.f));
        atomicAdd(dst + 2, fmaxf((f2 - mu) * inv * lg.z + lb.z, 0.f));
        atomicAdd(dst + 3, fmaxf((f3 - mu) * inv * lg.w + lb.w, 0.f));
        if (lane == 0) atomicAdd(&cnt[vox], 1.f);
    }
}

// ---------------- pooled sums / counts -> fp32 + fp16 -------------------------
__global__ void pool_div_kernel(float* __restrict__ x, const float* __restrict__ cnt,
                                __half* __restrict__ xh, int M) {
    int total = M * CCH;
    for (int i = blockIdx.x * blockDim.x + threadIdx.x; i < total; i += gridDim.x * blockDim.x) {
        float v = x[i] / cnt[i >> 7];
        x[i] = v;
        xh[i] = __float2half(v);
    }
}

// ---------------- submanifold conv, fp16 mma.sync, cp.async double-buffered ---
// 256x128 tile / 512 threads (16 warps, 8x2). Fragment-level activity skip:
// warps skip ldsm+mma for 16-row fragments whose rows are all masked out
// (those rows were staged as exact zeros, so skipping is exact).
__global__ __launch_bounds__(512, 1)
void subm_conv_mma_kernel(const __half* __restrict__ xin,
                          const __half* __restrict__ W,   // 27 x 128 x 128 fp16
                          const int*   __restrict__ nbr_idx,
                          const float* __restrict__ nbr_mask,
                          float* __restrict__ y,
                          float* __restrict__ gstats,
                          int M) {
    extern __shared__ __align__(16) char smem_raw[];
    int* sidx = (int*)(smem_raw + 2 * ATILE + 2 * BTILE);   // 27 x 256
    __shared__ int   s_act[27], s_sal[27], s_nact;
    __shared__ float sstat[CCH], ssq[CCH];

    const int tid  = threadIdx.x;
    const int warp = tid >> 5, lane = tid & 31;
    const int wm = warp >> 1;
    const int wn = warp & 1;
    const int v0 = blockIdx.x * BM;

    for (int j = tid; j < 27 * BM; j += 512) {
        int r = j / 27, o = j - r * 27;
        int v = v0 + r;
        int id = -1;
        if (v < M && nbr_mask[(size_t)v0 * 27 + j] != 0.f)
            id = nbr_idx[(size_t)v0 * 27 + j];
        sidx[o * BM + r] = id;
    }
    if (tid < 27) s_act[tid] = 0;
    if (tid < CCH) { sstat[tid] = 0.f; ssq[tid] = 0.f; }
    __syncthreads();
    if (warp < 8) {
#pragma unroll 1
        for (int o = 0; o < 27; ++o) {
            unsigned bal = __ballot_sync(0xffffffffu, sidx[o * BM + warp * 32 + lane] >= 0);
            if (lane == 0 && bal) s_act[o] = 1;
        }
    }
    __syncthreads();
    if (tid == 0) {
        int n = 0;
        for (int o = 0; o < 27; ++o) if (s_act[o]) s_sal[n++] = o;
        s_nact = n;
    }
    __syncthreads();
    const int nact = s_nact;

    const unsigned sAu = smem_u32(smem_raw);
    const unsigned sBu = sAu + 2 * ATILE;
    const int arow = tid >> 1;
    const int ac0  = (tid & 1) * 8;
    const int brow = tid >> 2;
    const int bc0  = (tid & 3) * 4;
    // fragment-activity probe row: lanes 0-15 -> frag0, 16-31 -> frag1
    const int frow = wm * 32 + (lane >> 4) * 16 + (lane & 15);

    float acc[2][8][4];
#pragma unroll
    for (int mi = 0; mi < 2; ++mi)
#pragma unroll
        for (int ni = 0; ni < 8; ++ni)
#pragma unroll
            for (int q = 0; q < 4; ++q) acc[mi][ni][q] = 0.f;

    {
        int o = s_sal[0];
        int id = sidx[o * BM + arow];
        unsigned ssz = (id >= 0) ? 16u : 0u;
        const __half* srcA = xin + (size_t)(id >= 0 ? id : 0) * CCH + ac0 * 8;
        const __half* srcB = W + (size_t)o * CCH * CCH + brow * CCH + bc0 * 8;
#pragma unroll
        for (int q = 0; q < 8; ++q)
            cp16z(sAu + swz(arow, ac0 + q), srcA + q * 8, ssz);
#pragma unroll
        for (int q = 0; q < 4; ++q)
            cp16 (sBu + swz(brow, bc0 + q), srcB + q * 8);
        asm volatile("cp.async.commit_group;\n" ::: "memory");
    }

    for (int t = 0; t < nact; ++t) {
        const int b = t & 1;
        const int o_cur = s_sal[t];
        // per-warp fragment activity for this offset (exact: inactive rows are zeros)
        unsigned abal = __ballot_sync(0xffffffffu, sidx[o_cur * BM + frow] >= 0);
        const bool act0 = (abal & 0xFFFFu) != 0u;
        const bool act1 = (abal >> 16) != 0u;

        asm volatile("cp.async.wait_group 0;\n" ::: "memory");
        __syncthreads();
        if (t + 1 < nact) {
            int o = s_sal[t + 1];
            int id = sidx[o * BM + arow];
            unsigned ssz = (id >= 0) ? 16u : 0u;
            const __half* srcA = xin + (size_t)(id >= 0 ? id : 0) * CCH + ac0 * 8;
            const __half* srcB = W + (size_t)o * CCH * CCH + brow * CCH + bc0 * 8;
            unsigned dA = sAu + (unsigned)((b ^ 1) * ATILE);
            unsigned dB = sBu + (unsigned)((b ^ 1) * BTILE);
#pragma unroll
            for (int q = 0; q < 8; ++q)
                cp16z(dA + swz(arow, ac0 + q), srcA + q * 8, ssz);
#pragma unroll
            for (int q = 0; q < 4; ++q)
                cp16 (dB + swz(brow, bc0 + q), srcB + q * 8);
            asm volatile("cp.async.commit_group;\n" ::: "memory");
        }

        if (act0 | act1) {
            const unsigned Ab = sAu + (unsigned)(b * ATILE);
            const unsigned Bb = sBu + (unsigned)(b * BTILE);
#pragma unroll
            for (int kc = 0; kc < 8; ++kc) {
                uint32_t a[2][4];
                if (act0) {
                    int row = wm * 32 + (lane & 15);
                    ldsm_x4(a[0], Ab + swz(row, kc * 2 + (lane >> 4)));
                }
                if (act1) {
                    int row = wm * 32 + 16 + (lane & 15);
                    ldsm_x4(a[1], Ab + swz(row, kc * 2 + (lane >> 4)));
                }
#pragma unroll
                for (int nb = 0; nb < 4; ++nb) {
                    uint32_t bb[4];
                    int row = kc * 16 + (lane & 15);
                    ldsm_x4_t(bb, Bb + swz(row, wn * 8 + nb * 2 + (lane >> 4)));
                    if (act0) {
                        mma_f16(acc[0][nb * 2 + 0], a[0], bb[0], bb[1]);
                        mma_f16(acc[0][nb * 2 + 1], a[0], bb[2], bb[3]);
                    }
                    if (act1) {
                        mma_f16(acc[1][nb * 2 + 0], a[1], bb[0], bb[1]);
                        mma_f16(acc[1][nb * 2 + 1], a[1], bb[2], bb[3]);
                    }
                }
            }
        }
        __syncthreads();
    }

    const int rbase = v0 + wm * 32 + (lane >> 2);
    const int cbase = wn * 64 + (lane & 3) * 2;
#pragma unroll
    for (int mi = 0; mi < 2; ++mi) {
#pragma unroll
        for (int ni = 0; ni < 8; ++ni) {
            int col = cbase + ni * 8;
            int r0 = rbase + mi * 16;
            if (r0 < M) {
                y[(size_t)r0 * CCH + col]     = acc[mi][ni][0];
                y[(size_t)r0 * CCH + col + 1] = acc[mi][ni][1];
            }
            int r1 = r0 + 8;
            if (r1 < M) {
                y[(size_t)r1 * CCH + col]     = acc[mi][ni][2];
                y[(size_t)r1 * CCH + col + 1] = acc[mi][ni][3];
            }
        }
    }
#pragma unroll
    for (int ni = 0; ni < 8; ++ni) {
#pragma unroll
        for (int tt = 0; tt < 2; ++tt) {
            float a0 = acc[0][ni][tt],     a1 = acc[0][ni][2 + tt];
            float a2 = acc[1][ni][tt],     a3 = acc[1][ni][2 + tt];
            float s = a0 + a1 + a2 + a3;
            float q = a0 * a0 + a1 * a1 + a2 * a2 + a3 * a3;
#pragma unroll
            for (int off = 4; off <= 16; off <<= 1) {
                s += __shfl_xor_sync(0xffffffffu, s, off);
                q += __shfl_xor_sync(0xffffffffu, q, off);
            }
            if ((lane >> 2) == 0) {
                int c = cbase + ni * 8 + tt;
                atomicAdd(&sstat[c], s);
                atomicAdd(&ssq[c], q);
            }
        }
    }
    __syncthreads();
    if (tid < CCH) {
        atomicAdd(&gstats[tid],       sstat[tid]);
        atomicAdd(&gstats[CCH + tid], ssq[tid]);
    }
}

// ---------------- BN apply: hoisted scale/bias (one rsqrt per channel/block) --
__global__ __launch_bounds__(256)
void bn_apply_kernel(const float* __restrict__ y,
                     const float* __restrict__ g,
                     const float* __restrict__ b,
                     const float* __restrict__ stats,
                     const float* __restrict__ residual,   // nullable
                     float* __restrict__ out_f32,          // nullable
                     __half* __restrict__ out_h16,         // nullable
                     int M) {
    __shared__ float sc[CCH], sb[CCH];
    float invM = 1.f / (float)M;
    if (threadIdx.x < CCH) {
        int c = threadIdx.x;
        float m   = stats[c] * invM;
        float var = stats[128 + c] * invM - m * m;
        float s = rsqrtf(var + EPSV) * g[c];
        sc[c] = s;
        sb[c] = b[c] - m * s;
    }
    __syncthreads();

    int total4 = M * 32;
    for (int i = blockIdx.x * blockDim.x + threadIdx.x; i < total4; i += gridDim.x * blockDim.x) {
        int c0 = (i & 31) * 4;
        float4 yv = ((const float4*)y)[i];
        float v0 = yv.x * sc[c0]     + sb[c0];
        float v1 = yv.y * sc[c0 + 1] + sb[c0 + 1];
        float v2 = yv.z * sc[c0 + 2] + sb[c0 + 2];
        float v3 = yv.w * sc[c0 + 3] + sb[c0 + 3];
        if (residual) {
            float4 rv = ((const float4*)residual)[i];
            v0 += rv.x; v1 += rv.y; v2 += rv.z; v3 += rv.w;
        }
        v0 = fmaxf(v0, 0.f); v1 = fmaxf(v1, 0.f);
        v2 = fmaxf(v2, 0.f); v3 = fmaxf(v3, 0.f);
        if (out_f32) ((float4*)out_f32)[i] = make_float4(v0, v1, v2, v3);
        if (out_h16) {
            ((__half2*)out_h16)[2 * i]     = __floats2half2_rn(v0, v1);
            ((__half2*)out_h16)[2 * i + 1] = __floats2half2_rn(v2, v3);
        }
    }
}

// ---------------- head on voxels: dvox = relu(x@w1+b1)@w2 + b2 ----------------
__global__ __launch_bounds__(256)
void head_vox_kernel(const __half* __restrict__ xh,
                     const __half* __restrict__ w1h,
                     const float* __restrict__ b1,
                     const float* __restrict__ w2,
                     const float* __restrict__ b2,
                     float* __restrict__ dvox,
                     int M) {
    extern __shared__ __align__(16) char smem_raw[];
    float* hs = (float*)(smem_raw + 49152);
    __shared__ float b1s[64], b2s[14], w2s[64 * 14];

    const int tid  = threadIdx.x;
    const int warp = tid >> 5, lane = tid & 31;
    const int v0 = blockIdx.x * 128;

    const unsigned sAu = smem_u32(smem_raw);
    const unsigned sBu = sAu + 32768u;

    {
        int row = tid >> 1, c0 = (tid & 1) * 8;
        unsigned ssz = (v0 + row < M) ? 16u : 0u;
        const __half* srcA = xh + (size_t)(v0 + row < M ? v0 + row : 0) * CCH + c0 * 8;
#pragma unroll
        for (int q = 0; q < 8; ++q)
            cp16z(sAu + swz(row, c0 + q), srcA + q * 8, ssz);
    }
    for (int j = tid; j < 1024; j += 256) {
        int row = j >> 3, c = j & 7;
        cp16(sBu + swz64(row, c), w1h + row * 64 + c * 8);
    }
    asm volatile("cp.async.commit_group;\n" ::: "memory");
    if (tid < 64) b1s[tid] = b1[tid];
    if (tid < 14) b2s[tid] = b2[tid];
    for (int j = tid; j < 64 * 14; j += 256) w2s[j] = w2[j];
    asm volatile("cp.async.wait_group 0;\n" ::: "memory");
    __syncthreads();

    float acc[8][4];
#pragma unroll
    for (int ni = 0; ni < 8; ++ni)
#pragma unroll
        for (int q = 0; q < 4; ++q) acc[ni][q] = 0.f;
#pragma unroll
    for (int kc = 0; kc < 8; ++kc) {
        uint32_t a[4];
        ldsm_x4(a, sAu + swz(warp * 16 + (lane & 15), kc * 2 + (lane >> 4)));
#pragma unroll
        for (int nb = 0; nb < 4; ++nb) {
            uint32_t bb[4];
            ldsm_x4_t(bb, sBu + swz64(kc * 16 + (lane & 15), nb * 2 + (lane >> 4)));
            mma_f16(acc[nb * 2 + 0], a, bb[0], bb[1]);
            mma_f16(acc[nb * 2 + 1], a, bb[2], bb[3]);
        }
    }
    {
        int r0 = warp * 16 + (lane >> 2);
        int c0 = (lane & 3) * 2;
#pragma unroll
        for (int ni = 0; ni < 8; ++ni) {
            int c = c0 + ni * 8;
            hs[r0 * 65 + c]           = fmaxf(acc[ni][0] + b1s[c], 0.f);
            hs[r0 * 65 + c + 1]       = fmaxf(acc[ni][1] + b1s[c + 1], 0.f);
            hs[(r0 + 8) * 65 + c]     = fmaxf(acc[ni][2] + b1s[c], 0.f);
            hs[(r0 + 8) * 65 + c + 1] = fmaxf(acc[ni][3] + b1s[c + 1], 0.f);
        }
    }
    __syncthreads();

    {
        int r = tid >> 1;
        int cb = (tid & 1) * 7;
        if (v0 + r < M) {
            float d[7];
#pragma unroll
            for (int c = 0; c < 7; ++c) d[c] = b2s[cb + c];
#pragma unroll 8
            for (int k = 0; k < 64; ++k) {
                float hv = hs[r * 65 + k];
#pragma unroll
                for (int c = 0; c < 7; ++c) d[c] += hv * w2s[k * 14 + cb + c];
            }
            float* dst = dvox + (size_t)(v0 + r) * 14 + cb;
#pragma unroll
            for (int c = 0; c < 7; ++c) dst[c] = d[c];
        }
    }
}

// ---------------- scatter: out = gp + dvox[inv_idx] ---------------------------
__global__ void scatter_out_kernel(const float* __restrict__ gp,
                                   const float* __restrict__ dvox,
                                   const int*   __restrict__ inv_idx,
                                   float* __restrict__ out, int Np) {
    int total = Np * 14;
    for (int t = blockIdx.x * blockDim.x + threadIdx.x; t < total; t += gridDim.x * blockDim.x) {
        int i = t / 14, j = t - i * 14;
        out[t] = gp[t] + dvox[(size_t)inv_idx[i] * 14 + j];
    }
}

// ---------------- launch -------------------------------------------------------
extern "C" void kernel_launch(void* const* d_in, const int* in_sizes, int n_in,
                              void* d_out, int out_size) {
    const float* gp       = (const float*)d_in[0];
    const float* w_enc    = (const float*)d_in[1];
    const float* b_enc    = (const float*)d_in[2];
    const float* ln_g     = (const float*)d_in[3];
    const float* ln_b     = (const float*)d_in[4];
    const float* conv_w   = (const float*)d_in[5];
    const float* bn_g     = (const float*)d_in[6];
    const float* bn_b     = (const float*)d_in[7];
    const float* w1       = (const float*)d_in[8];
    const float* b1       = (const float*)d_in[9];
    const float* w2       = (const float*)d_in[10];
    const float* b2       = (const float*)d_in[11];
    const float* nbr_mask = (const float*)d_in[12];
    const int*   inv_idx  = (const int*)d_in[13];
    const int*   nbr_idx  = (const int*)d_in[14];
    float* out = (float*)d_out;

    const int Np = in_sizes[0] / 14;
    const int M  = in_sizes[12] / 27;

    float *px, *py, *pcnt, *pstats;
    __half *pxh, *pah, *pwh, *pw1h;
    cudaGetSymbolAddress((void**)&px,     g_x);
    cudaGetSymbolAddress((void**)&py,     g_y);
    cudaGetSymbolAddress((void**)&pxh,    g_xh);
    cudaGetSymbolAddress((void**)&pah,    g_ah);
    cudaGetSymbolAddress((void**)&pwh,    g_wh);
    cudaGetSymbolAddress((void**)&pw1h,   g_w1h);
    cudaGetSymbolAddress((void**)&pcnt,   g_cnt);
    cudaGetSymbolAddress((void**)&pstats, g_stats);

    const int CONV_SMEM = 2 * ATILE + 2 * BTILE + 27 * BM * 4;  // 224256
    cudaFuncSetAttribute(subm_conv_mma_kernel,
                         cudaFuncAttributeMaxDynamicSharedMemorySize, CONV_SMEM);
    const int HEAD_SMEM = 49152 + 128 * 65 * 4;                 // 82432
    cudaFuncSetAttribute(head_vox_kernel,
                         cudaFuncAttributeMaxDynamicSharedMemorySize, HEAD_SMEM);

    convert_w_kernel<<<1024, 256>>>(conv_w, pwh, 4 * 27 * CCH * CCH);
    convert_w_kernel<<<8, 256>>>(w1, pw1h, CCH * 64);
    cudaMemsetAsync(px, 0, (size_t)M * CCH * sizeof(float));
    cudaMemsetAsync(pcnt, 0, (size_t)M * sizeof(float));
    encode_pool_kernel<<<512, 256>>>(gp, w_enc, b_enc, ln_g, ln_b, inv_idx, px, pcnt, Np);
    pool_div_kernel<<<2048, 256>>>(px, pcnt, pxh, M);

    const int tiles = (M + BM - 1) / BM;
    for (int blk = 0; blk < 2; ++blk) {
        const int l0 = 2 * blk, l1 = 2 * blk + 1;
        cudaMemsetAsync(pstats, 0, 256 * sizeof(float));
        subm_conv_mma_kernel<<<tiles, 512, CONV_SMEM>>>(
            pxh, pwh + (size_t)l0 * 27 * CCH * CCH, nbr_idx, nbr_mask, py, pstats, M);
        bn_apply_kernel<<<2048, 256>>>(py, bn_g + l0 * CCH, bn_b + l0 * CCH, pstats,
                                       (const float*)0, (float*)0, pah, M);
        cudaMemsetAsync(pstats, 0, 256 * sizeof(float));
        subm_conv_mma_kernel<<<tiles, 512, CONV_SMEM>>>(
            pah, pwh + (size_t)l1 * 27 * CCH * CCH, nbr_idx, nbr_mask, py, pstats, M);
        if (blk == 0) {
            bn_apply_kernel<<<2048, 256>>>(py, bn_g + l1 * CCH, bn_b + l1 * CCH, pstats,
                                           px, px, pxh, M);
        } else {
            bn_apply_kernel<<<2048, 256>>>(py, bn_g + l1 * CCH, bn_b + l1 * CCH, pstats,
                                           px, (float*)0, pxh, M);
        }
    }

    head_vox_kernel<<<(M + 127) / 128, 256, HEAD_SMEM>>>(pxh, pw1h, b1, w2, b2, py, M);
    scatter_out_kernel<<<2048, 256>>>(gp, py, inv_idx, out, Np);
}

// round 10
// speedup vs baseline: 1.7045x; 1.0149x over previous
#include <cuda_runtime.h>
#include <cuda_fp16.h>
#include <stdint.h>
#include <math.h>

#define NPTS 200000
#define CCH  128
#define EPSV 1e-5f
#define ATILE 65536u            // 256 x 128 halfs, swizzled
#define BTILE 32768u            // 128 x 128 halfs, swizzled
#define BM    256

// ---------------- scratch (device globals; no allocations anywhere) ----------
__device__ float  g_x[NPTS * CCH];           // fp32 pooled sums (encoder)
__device__ float  g_y[NPTS * CCH];           // fp32 conv output / dvox
__device__ __half g_xh[NPTS * CCH];          // fp16 x path (input / residual)
__device__ __half g_ah[NPTS * CCH];          // fp16 mid path
__device__ __half g_wh[4 * 27 * CCH * CCH];  // fp16 conv weights
__device__ __half g_w1h[CCH * 64];           // fp16 head weights
__device__ float  g_cnt[NPTS];
__device__ float  g_stats[256];              // [0..127]=sum [128..255]=sumsq

// ---------------- helpers ----------------
__device__ __forceinline__ unsigned smem_u32(const void* p) {
    return (unsigned)__cvta_generic_to_shared(p);
}
__device__ __forceinline__ unsigned swz(int row, int c16) {
    return (unsigned)(row * 256 + (((c16) ^ (row & 7)) << 4));
}
__device__ __forceinline__ unsigned swz64(int row, int c16) {
    return (unsigned)(row * 128 + (((c16) ^ (row & 7)) << 4));
}
__device__ __forceinline__ void ldsm_x4(uint32_t* r, unsigned addr) {
    asm volatile("ldmatrix.sync.aligned.m8n8.x4.shared.b16 {%0,%1,%2,%3}, [%4];\n"
                 : "=r"(r[0]), "=r"(r[1]), "=r"(r[2]), "=r"(r[3]) : "r"(addr));
}
__device__ __forceinline__ void ldsm_x4_t(uint32_t* r, unsigned addr) {
    asm volatile("ldmatrix.sync.aligned.m8n8.x4.trans.shared.b16 {%0,%1,%2,%3}, [%4];\n"
                 : "=r"(r[0]), "=r"(r[1]), "=r"(r[2]), "=r"(r[3]) : "r"(addr));
}
__device__ __forceinline__ void mma_f16(float* c, const uint32_t* a, uint32_t b0, uint32_t b1) {
    asm volatile("mma.sync.aligned.m16n8k16.row.col.f32.f16.f16.f32 "
                 "{%0,%1,%2,%3}, {%4,%5,%6,%7}, {%8,%9}, {%0,%1,%2,%3};\n"
                 : "+f"(c[0]), "+f"(c[1]), "+f"(c[2]), "+f"(c[3])
                 : "r"(a[0]), "r"(a[1]), "r"(a[2]), "r"(a[3]), "r"(b0), "r"(b1));
}
__device__ __forceinline__ void cp16(unsigned dst, const void* src) {
    asm volatile("cp.async.cg.shared.global [%0], [%1], 16;\n" :: "r"(dst), "l"(src));
}
__device__ __forceinline__ void cp16z(unsigned dst, const void* src, unsigned ssz) {
    asm volatile("cp.async.cg.shared.global [%0], [%1], 16, %2;\n"
                 :: "r"(dst), "l"(src), "r"(ssz));
}

// ---------------- weight fp32 -> fp16 ----------------
__global__ void convert_w_kernel(const float* __restrict__ w, __half* __restrict__ wh, int n) {
    for (int i = blockIdx.x * blockDim.x + threadIdx.x; i < n; i += gridDim.x * blockDim.x)
        wh[i] = __float2half(w[i]);
}

// ---------------- encoder: warp-per-point Linear+LN+ReLU + segment-sum --------
__global__ __launch_bounds__(256)
void encode_pool_kernel(const float* __restrict__ gp,
                        const float* __restrict__ w_enc,
                        const float* __restrict__ b_enc,
                        const float* __restrict__ ln_g,
                        const float* __restrict__ ln_b,
                        const int*   __restrict__ inv_idx,
                        float* __restrict__ xsum,
                        float* __restrict__ cnt,
                        int Np) {
    const int lane = threadIdx.x & 31;
    const int gw = (blockIdx.x * blockDim.x + threadIdx.x) >> 5;
    const int nw = (gridDim.x * blockDim.x) >> 5;
    const int c0 = lane * 4;

    float wreg[14][4];
#pragma unroll
    for (int k = 0; k < 14; ++k) {
        float4 t = *(const float4*)(w_enc + k * CCH + c0);
        wreg[k][0] = t.x; wreg[k][1] = t.y; wreg[k][2] = t.z; wreg[k][3] = t.w;
    }
    float4 be = *(const float4*)(b_enc + c0);
    float4 lg = *(const float4*)(ln_g + c0);
    float4 lb = *(const float4*)(ln_b + c0);

    for (int i = gw; i < Np; i += nw) {
        float gv = (lane < 14) ? gp[(size_t)i * 14 + lane] : 0.f;
        float f0 = be.x, f1 = be.y, f2 = be.z, f3 = be.w;
#pragma unroll
        for (int k = 0; k < 14; ++k) {
            float s = __shfl_sync(0xffffffffu, gv, k);
            f0 += s * wreg[k][0]; f1 += s * wreg[k][1];
            f2 += s * wreg[k][2]; f3 += s * wreg[k][3];
        }
        float s1 = f0 + f1 + f2 + f3;
        float s2 = f0 * f0 + f1 * f1 + f2 * f2 + f3 * f3;
#pragma unroll
        for (int off = 16; off > 0; off >>= 1) {
            s1 += __shfl_xor_sync(0xffffffffu, s1, off);
            s2 += __shfl_xor_sync(0xffffffffu, s2, off);
        }
        float mu  = s1 * (1.f / 128.f);
        float inv = rsqrtf(s2 * (1.f / 128.f) - mu * mu + EPSV);
        int vox = inv_idx[i];
        float* dst = xsum + (size_t)vox * CCH + c0;
        atomicAdd(dst + 0, fmaxf((f0 - mu) * inv * lg.x + lb.x, 0.f));
        atomicAdd(dst + 1, fmaxf((f1 - mu) * inv * lg.y + lb.y, 0.f));
        atomicAdd(dst + 2, fmaxf((f2 - mu) * inv * lg.z + lb.z, 0.f));
        atomicAdd(dst + 3, fmaxf((f3 - mu) * inv * lg.w + lb.w, 0.f));
        if (lane == 0) atomicAdd(&cnt[vox], 1.f);
    }
}

// ---------------- pooled sums / counts -> fp16 only ---------------------------
__global__ void pool_div_kernel(const float* __restrict__ x, const float* __restrict__ cnt,
                                __half* __restrict__ xh, int M) {
    int total = M * CCH;
    for (int i = blockIdx.x * blockDim.x + threadIdx.x; i < total; i += gridDim.x * blockDim.x)
        xh[i] = __float2half(x[i] / cnt[i >> 7]);
}

// ---------------- submanifold conv, fp16 mma.sync, cp.async double-buffered ---
// 256x128 tile / 512 threads (16 warps, 8x2). Per-offset 16-bit fragment
// activity mask (precomputed): inactive 16-row fragments skip BOTH staging and
// mma (their rows are never read; rows inside active fragments that are masked
// out stage exact zeros via cp.async src-size-0, so skipping is exact).
__global__ __launch_bounds__(512, 1)
void subm_conv_mma_kernel(const __half* __restrict__ xin,
                          const __half* __restrict__ W,   // 27 x 128 x 128 fp16
                          const int*   __restrict__ nbr_idx,
                          const float* __restrict__ nbr_mask,
                          float* __restrict__ y,
                          float* __restrict__ gstats,
                          int M) {
    extern __shared__ __align__(16) char smem_raw[];
    int* sidx = (int*)(smem_raw + 2 * ATILE + 2 * BTILE);   // 27 x 256
    __shared__ unsigned s_fmask[27];
    __shared__ int   s_sal[27], s_nact;
    __shared__ float sstat[CCH], ssq[CCH];

    const int tid  = threadIdx.x;
    const int warp = tid >> 5, lane = tid & 31;
    const int wm = warp >> 1;
    const int wn = warp & 1;
    const int v0 = blockIdx.x * BM;

    for (int j = tid; j < 27 * BM; j += 512) {
        int r = j / 27, o = j - r * 27;
        int v = v0 + r;
        int id = -1;
        if (v < M && nbr_mask[(size_t)v0 * 27 + j] != 0.f)
            id = nbr_idx[(size_t)v0 * 27 + j];
        sidx[o * BM + r] = id;
    }
    if (tid < 27) s_fmask[tid] = 0u;
    if (tid < CCH) { sstat[tid] = 0.f; ssq[tid] = 0.f; }
    __syncthreads();
    // fragment activity: 27 offsets x 16 fragments of 16 rows
    if (tid < 432) {
        int o = tid >> 4, f = tid & 15;
        const int* p = sidx + o * BM + f * 16;
        int any = 0;
#pragma unroll
        for (int i = 0; i < 16; ++i) any |= (p[i] >= 0);
        if (any) atomicOr(&s_fmask[o], 1u << f);
    }
    __syncthreads();
    if (tid == 0) {
        int n = 0;
        for (int o = 0; o < 27; ++o) if (s_fmask[o]) s_sal[n++] = o;
        s_nact = n;
    }
    __syncthreads();
    const int nact = s_nact;

    const unsigned sAu = smem_u32(smem_raw);
    const unsigned sBu = sAu + 2 * ATILE;
    const int arow = tid >> 1;
    const int ac0  = (tid & 1) * 8;
    const int afrag = arow >> 4;
    const int brow = tid >> 2;
    const int bc0  = (tid & 3) * 4;

    float acc[2][8][4];
#pragma unroll
    for (int mi = 0; mi < 2; ++mi)
#pragma unroll
        for (int ni = 0; ni < 8; ++ni)
#pragma unroll
            for (int q = 0; q < 4; ++q) acc[mi][ni][q] = 0.f;

    {   // stage offset 0 into buffer 0
        int o = s_sal[0];
        if ((s_fmask[o] >> afrag) & 1u) {
            int id = sidx[o * BM + arow];
            unsigned ssz = (id >= 0) ? 16u : 0u;
            const __half* srcA = xin + (size_t)(id >= 0 ? id : 0) * CCH + ac0 * 8;
#pragma unroll
            for (int q = 0; q < 8; ++q)
                cp16z(sAu + swz(arow, ac0 + q), srcA + q * 8, ssz);
        }
        const __half* srcB = W + (size_t)o * CCH * CCH + brow * CCH + bc0 * 8;
#pragma unroll
        for (int q = 0; q < 4; ++q)
            cp16 (sBu + swz(brow, bc0 + q), srcB + q * 8);
        asm volatile("cp.async.commit_group;\n" ::: "memory");
    }

    for (int t = 0; t < nact; ++t) {
        const int b = t & 1;
        const unsigned fmask = s_fmask[s_sal[t]];
        const bool act0 = (fmask >> (2 * wm)) & 1u;
        const bool act1 = (fmask >> (2 * wm + 1)) & 1u;

        asm volatile("cp.async.wait_group 0;\n" ::: "memory");
        __syncthreads();
        if (t + 1 < nact) {
            int o = s_sal[t + 1];
            unsigned dA = sAu + (unsigned)((b ^ 1) * ATILE);
            unsigned dB = sBu + (unsigned)((b ^ 1) * BTILE);
            if ((s_fmask[o] >> afrag) & 1u) {
                int id = sidx[o * BM + arow];
                unsigned ssz = (id >= 0) ? 16u : 0u;
                const __half* srcA = xin + (size_t)(id >= 0 ? id : 0) * CCH + ac0 * 8;
#pragma unroll
                for (int q = 0; q < 8; ++q)
                    cp16z(dA + swz(arow, ac0 + q), srcA + q * 8, ssz);
            }
            const __half* srcB = W + (size_t)o * CCH * CCH + brow * CCH + bc0 * 8;
#pragma unroll
            for (int q = 0; q < 4; ++q)
                cp16 (dB + swz(brow, bc0 + q), srcB + q * 8);
            asm volatile("cp.async.commit_group;\n" ::: "memory");
        }

        if (act0 | act1) {
            const unsigned Ab = sAu + (unsigned)(b * ATILE);
            const unsigned Bb = sBu + (unsigned)(b * BTILE);
#pragma unroll
            for (int kc = 0; kc < 8; ++kc) {
                uint32_t a[2][4];
                if (act0) {
                    int row = wm * 32 + (lane & 15);
                    ldsm_x4(a[0], Ab + swz(row, kc * 2 + (lane >> 4)));
                }
                if (act1) {
                    int row = wm * 32 + 16 + (lane & 15);
                    ldsm_x4(a[1], Ab + swz(row, kc * 2 + (lane >> 4)));
                }
#pragma unroll
                for (int nb = 0; nb < 4; ++nb) {
                    uint32_t bb[4];
                    int row = kc * 16 + (lane & 15);
                    ldsm_x4_t(bb, Bb + swz(row, wn * 8 + nb * 2 + (lane >> 4)));
                    if (act0) {
                        mma_f16(acc[0][nb * 2 + 0], a[0], bb[0], bb[1]);
                        mma_f16(acc[0][nb * 2 + 1], a[0], bb[2], bb[3]);
                    }
                    if (act1) {
                        mma_f16(acc[1][nb * 2 + 0], a[1], bb[0], bb[1]);
                        mma_f16(acc[1][nb * 2 + 1], a[1], bb[2], bb[3]);
                    }
                }
            }
        }
        __syncthreads();
    }

    const int rbase = v0 + wm * 32 + (lane >> 2);
    const int cbase = wn * 64 + (lane & 3) * 2;
#pragma unroll
    for (int mi = 0; mi < 2; ++mi) {
#pragma unroll
        for (int ni = 0; ni < 8; ++ni) {
            int col = cbase + ni * 8;
            int r0 = rbase + mi * 16;
            if (r0 < M) {
                y[(size_t)r0 * CCH + col]     = acc[mi][ni][0];
                y[(size_t)r0 * CCH + col + 1] = acc[mi][ni][1];
            }
            int r1 = r0 + 8;
            if (r1 < M) {
                y[(size_t)r1 * CCH + col]     = acc[mi][ni][2];
                y[(size_t)r1 * CCH + col + 1] = acc[mi][ni][3];
            }
        }
    }
#pragma unroll
    for (int ni = 0; ni < 8; ++ni) {
#pragma unroll
        for (int tt = 0; tt < 2; ++tt) {
            float a0 = acc[0][ni][tt],     a1 = acc[0][ni][2 + tt];
            float a2 = acc[1][ni][tt],     a3 = acc[1][ni][2 + tt];
            float s = a0 + a1 + a2 + a3;
            float q = a0 * a0 + a1 * a1 + a2 * a2 + a3 * a3;
#pragma unroll
            for (int off = 4; off <= 16; off <<= 1) {
                s += __shfl_xor_sync(0xffffffffu, s, off);
                q += __shfl_xor_sync(0xffffffffu, q, off);
            }
            if ((lane >> 2) == 0) {
                int c = cbase + ni * 8 + tt;
                atomicAdd(&sstat[c], s);
                atomicAdd(&ssq[c], q);
            }
        }
    }
    __syncthreads();
    if (tid < CCH) {
        atomicAdd(&gstats[tid],       sstat[tid]);
        atomicAdd(&gstats[CCH + tid], ssq[tid]);
    }
}

// ---------------- BN apply: hoisted scale/bias, fp16 residual, fp16 out -------
__global__ __launch_bounds__(256)
void bn_apply_kernel(const float* __restrict__ y,
                     const float* __restrict__ g,
                     const float* __restrict__ b,
                     const float* __restrict__ stats,
                     const __half* __restrict__ residual,   // nullable (fp16)
                     __half* __restrict__ out_h16,
                     int M) {
    __shared__ float sc[CCH], sb[CCH];
    float invM = 1.f / (float)M;
    if (threadIdx.x < CCH) {
        int c = threadIdx.x;
        float m   = stats[c] * invM;
        float var = stats[128 + c] * invM - m * m;
        float s = rsqrtf(var + EPSV) * g[c];
        sc[c] = s;
        sb[c] = b[c] - m * s;
    }
    __syncthreads();

    int total4 = M * 32;
    for (int i = blockIdx.x * blockDim.x + threadIdx.x; i < total4; i += gridDim.x * blockDim.x) {
        int c0 = (i & 31) * 4;
        float4 yv = ((const float4*)y)[i];
        float v0 = yv.x * sc[c0]     + sb[c0];
        float v1 = yv.y * sc[c0 + 1] + sb[c0 + 1];
        float v2 = yv.z * sc[c0 + 2] + sb[c0 + 2];
        float v3 = yv.w * sc[c0 + 3] + sb[c0 + 3];
        if (residual) {
            __half2 r01 = ((const __half2*)residual)[2 * i];
            __half2 r23 = ((const __half2*)residual)[2 * i + 1];
            float2 f01 = __half22float2(r01);
            float2 f23 = __half22float2(r23);
            v0 += f01.x; v1 += f01.y; v2 += f23.x; v3 += f23.y;
        }
        v0 = fmaxf(v0, 0.f); v1 = fmaxf(v1, 0.f);
        v2 = fmaxf(v2, 0.f); v3 = fmaxf(v3, 0.f);
        ((__half2*)out_h16)[2 * i]     = __floats2half2_rn(v0, v1);
        ((__half2*)out_h16)[2 * i + 1] = __floats2half2_rn(v2, v3);
    }
}

// ---------------- head on voxels: dvox = relu(x@w1+b1)@w2 + b2 ----------------
__global__ __launch_bounds__(256)
void head_vox_kernel(const __half* __restrict__ xh,
                     const __half* __restrict__ w1h,
                     const float* __restrict__ b1,
                     const float* __restrict__ w2,
                     const float* __restrict__ b2,
                     float* __restrict__ dvox,
                     int M) {
    extern __shared__ __align__(16) char smem_raw[];
    float* hs = (float*)(smem_raw + 49152);
    __shared__ float b1s[64], b2s[14], w2s[64 * 14];

    const int tid  = threadIdx.x;
    const int warp = tid >> 5, lane = tid & 31;
    const int v0 = blockIdx.x * 128;

    const unsigned sAu = smem_u32(smem_raw);
    const unsigned sBu = sAu + 32768u;

    {
        int row = tid >> 1, c0 = (tid & 1) * 8;
        unsigned ssz = (v0 + row < M) ? 16u : 0u;
        const __half* srcA = xh + (size_t)(v0 + row < M ? v0 + row : 0) * CCH + c0 * 8;
#pragma unroll
        for (int q = 0; q < 8; ++q)
            cp16z(sAu + swz(row, c0 + q), srcA + q * 8, ssz);
    }
    for (int j = tid; j < 1024; j += 256) {
        int row = j >> 3, c = j & 7;
        cp16(sBu + swz64(row, c), w1h + row * 64 + c * 8);
    }
    asm volatile("cp.async.commit_group;\n" ::: "memory");
    if (tid < 64) b1s[tid] = b1[tid];
    if (tid < 14) b2s[tid] = b2[tid];
    for (int j = tid; j < 64 * 14; j += 256) w2s[j] = w2[j];
    asm volatile("cp.async.wait_group 0;\n" ::: "memory");
    __syncthreads();

    float acc[8][4];
#pragma unroll
    for (int ni = 0; ni < 8; ++ni)
#pragma unroll
        for (int q = 0; q < 4; ++q) acc[ni][q] = 0.f;
#pragma unroll
    for (int kc = 0; kc < 8; ++kc) {
        uint32_t a[4];
        ldsm_x4(a, sAu + swz(warp * 16 + (lane & 15), kc * 2 + (lane >> 4)));
#pragma unroll
        for (int nb = 0; nb < 4; ++nb) {
            uint32_t bb[4];
            ldsm_x4_t(bb, sBu + swz64(kc * 16 + (lane & 15), nb * 2 + (lane >> 4)));
            mma_f16(acc[nb * 2 + 0], a, bb[0], bb[1]);
            mma_f16(acc[nb * 2 + 1], a, bb[2], bb[3]);
        }
    }
    {
        int r0 = warp * 16 + (lane >> 2);
        int c0 = (lane & 3) * 2;
#pragma unroll
        for (int ni = 0; ni < 8; ++ni) {
            int c = c0 + ni * 8;
            hs[r0 * 65 + c]           = fmaxf(acc[ni][0] + b1s[c], 0.f);
            hs[r0 * 65 + c + 1]       = fmaxf(acc[ni][1] + b1s[c + 1], 0.f);
            hs[(r0 + 8) * 65 + c]     = fmaxf(acc[ni][2] + b1s[c], 0.f);
            hs[(r0 + 8) * 65 + c + 1] = fmaxf(acc[ni][3] + b1s[c + 1], 0.f);
        }
    }
    __syncthreads();

    {
        int r = tid >> 1;
        int cb = (tid & 1) * 7;
        if (v0 + r < M) {
            float d[7];
#pragma unroll
            for (int c = 0; c < 7; ++c) d[c] = b2s[cb + c];
#pragma unroll 8
            for (int k = 0; k < 64; ++k) {
                float hv = hs[r * 65 + k];
#pragma unroll
                for (int c = 0; c < 7; ++c) d[c] += hv * w2s[k * 14 + cb + c];
            }
            float* dst = dvox + (size_t)(v0 + r) * 14 + cb;
#pragma unroll
            for (int c = 0; c < 7; ++c) dst[c] = d[c];
        }
    }
}

// ---------------- scatter: out = gp + dvox[inv_idx], thread-per-point ---------
__global__ void scatter_out_kernel(const float* __restrict__ gp,
                                   const float* __restrict__ dvox,
                                   const int*   __restrict__ inv_idx,
                                   float* __restrict__ out, int Np) {
    for (int i = blockIdx.x * blockDim.x + threadIdx.x; i < Np; i += gridDim.x * blockDim.x) {
        const float* dr = dvox + (size_t)inv_idx[i] * 14;
        const float* gr = gp + (size_t)i * 14;
        float* orow = out + (size_t)i * 14;
#pragma unroll
        for (int j = 0; j < 14; ++j) orow[j] = gr[j] + dr[j];
    }
}

// ---------------- launch -------------------------------------------------------
extern "C" void kernel_launch(void* const* d_in, const int* in_sizes, int n_in,
                              void* d_out, int out_size) {
    const float* gp       = (const float*)d_in[0];
    const float* w_enc    = (const float*)d_in[1];
    const float* b_enc    = (const float*)d_in[2];
    const float* ln_g     = (const float*)d_in[3];
    const float* ln_b     = (const float*)d_in[4];
    const float* conv_w   = (const float*)d_in[5];
    const float* bn_g     = (const float*)d_in[6];
    const float* bn_b     = (const float*)d_in[7];
    const float* w1       = (const float*)d_in[8];
    const float* b1       = (const float*)d_in[9];
    const float* w2       = (const float*)d_in[10];
    const float* b2       = (const float*)d_in[11];
    const float* nbr_mask = (const float*)d_in[12];
    const int*   inv_idx  = (const int*)d_in[13];
    const int*   nbr_idx  = (const int*)d_in[14];
    float* out = (float*)d_out;

    const int Np = in_sizes[0] / 14;
    const int M  = in_sizes[12] / 27;

    float *px, *py, *pcnt, *pstats;
    __half *pxh, *pah, *pwh, *pw1h;
    cudaGetSymbolAddress((void**)&px,     g_x);
    cudaGetSymbolAddress((void**)&py,     g_y);
    cudaGetSymbolAddress((void**)&pxh,    g_xh);
    cudaGetSymbolAddress((void**)&pah,    g_ah);
    cudaGetSymbolAddress((void**)&pwh,    g_wh);
    cudaGetSymbolAddress((void**)&pw1h,   g_w1h);
    cudaGetSymbolAddress((void**)&pcnt,   g_cnt);
    cudaGetSymbolAddress((void**)&pstats, g_stats);

    const int CONV_SMEM = 2 * ATILE + 2 * BTILE + 27 * BM * 4;  // 224256
    cudaFuncSetAttribute(subm_conv_mma_kernel,
                         cudaFuncAttributeMaxDynamicSharedMemorySize, CONV_SMEM);
    const int HEAD_SMEM = 49152 + 128 * 65 * 4;                 // 82432
    cudaFuncSetAttribute(head_vox_kernel,
                         cudaFuncAttributeMaxDynamicSharedMemorySize, HEAD_SMEM);

    convert_w_kernel<<<1024, 256>>>(conv_w, pwh, 4 * 27 * CCH * CCH);
    convert_w_kernel<<<8, 256>>>(w1, pw1h, CCH * 64);
    cudaMemsetAsync(px, 0, (size_t)M * CCH * sizeof(float));
    cudaMemsetAsync(pcnt, 0, (size_t)M * sizeof(float));
    encode_pool_kernel<<<512, 256>>>(gp, w_enc, b_enc, ln_g, ln_b, inv_idx, px, pcnt, Np);
    pool_div_kernel<<<2048, 256>>>(px, pcnt, pxh, M);

    const int tiles = (M + BM - 1) / BM;
    for (int blk = 0; blk < 2; ++blk) {
        const int l0 = 2 * blk, l1 = 2 * blk + 1;
        // conv1 (fused BN stats) -> BN apply -> ReLU (fp16 out)
        cudaMemsetAsync(pstats, 0, 256 * sizeof(float));
        subm_conv_mma_kernel<<<tiles, 512, CONV_SMEM>>>(
            pxh, pwh + (size_t)l0 * 27 * CCH * CCH, nbr_idx, nbr_mask, py, pstats, M);
        bn_apply_kernel<<<2048, 256>>>(py, bn_g + l0 * CCH, bn_b + l0 * CCH, pstats,
                                       (const __half*)0, pah, M);
        // conv2 (fused BN stats) -> BN apply + fp16 residual -> ReLU (in-place xh)
        cudaMemsetAsync(pstats, 0, 256 * sizeof(float));
        subm_conv_mma_kernel<<<tiles, 512, CONV_SMEM>>>(
            pah, pwh + (size_t)l1 * 27 * CCH * CCH, nbr_idx, nbr_mask, py, pstats, M);
        bn_apply_kernel<<<2048, 256>>>(py, bn_g + l1 * CCH, bn_b + l1 * CCH, pstats,
                                       pxh, pxh, M);
    }

    head_vox_kernel<<<(M + 127) / 128, 256, HEAD_SMEM>>>(pxh, pw1h, b1, w2, b2, py, M);
    scatter_out_kernel<<<1024, 256>>>(gp, py, inv_idx, out, Np);
}